// round 8
// baseline (speedup 1.0000x reference)
#include <cuda_runtime.h>
#include <cuda_fp16.h>
#include <math.h>
#include <stdint.h>

#define ALPHA 0.2f

static constexpr int Bb = 8;     // batch
static constexpr int Nn = 2048;  // nodes
static constexpr int Ff = 256;   // features (Fin == Fout)

// ---------------------------------------------------------------------------
// Scratch (__device__ globals: allocation-free rule)
// ---------------------------------------------------------------------------
__device__ __align__(1024) __half g_hf[(size_t)Bb * Nn * Ff];     // h as fp16
__device__ __align__(1024) __half g_wt[Ff * Ff];                  // W^T fp16
__device__ __align__(1024) __half g_wht[(size_t)Bb * Ff * Nn];    // WhT fp16
__device__ __align__(16)   float g_s1[Bb * Nn];
__device__ __align__(16)   float g_s2[Bb * Nn];
__device__ __align__(16)   float g_wa[2 * Ff];
__device__ __align__(16)   float g_m2[Bb];                        // max_j s2[b,j]

// ---------------------------------------------------------------------------
// Helpers (baseline PTX only: mma.sync / ldmatrix / cp.async)
// ---------------------------------------------------------------------------
__device__ __forceinline__ uint32_t smem_u32(const void* p) {
    uint32_t a;
    asm("{ .reg .u64 t; cvta.to.shared.u64 t, %1; cvt.u32.u64 %0, t; }" : "=r"(a) : "l"(p));
    return a;
}
#define LDSM4(r0, r1, r2, r3, addr) \
    asm volatile("ldmatrix.sync.aligned.m8n8.x4.shared.b16 {%0,%1,%2,%3}, [%4];" \
                 : "=r"(r0), "=r"(r1), "=r"(r2), "=r"(r3) : "r"(addr))
#define MMA16816(d, a, b) \
    asm volatile("mma.sync.aligned.m16n8k16.row.col.f32.f16.f16.f32 " \
                 "{%0,%1,%2,%3},{%4,%5,%6,%7},{%8,%9},{%0,%1,%2,%3};" \
                 : "+f"((d)[0]), "+f"((d)[1]), "+f"((d)[2]), "+f"((d)[3]) \
                 : "r"((a)[0]), "r"((a)[1]), "r"((a)[2]), "r"((a)[3]), \
                   "r"((b)[0]), "r"((b)[1]))
#define CPA16(s, g) asm volatile("cp.async.cg.shared.global [%0], [%1], 16;" :: "r"(s), "l"(g))
#define CPCOMMIT()  asm volatile("cp.async.commit_group;" ::: "memory")
#define CPWAIT(n)   asm volatile("cp.async.wait_group %0;" :: "n"(n) : "memory")

__device__ __forceinline__ unsigned packh2(__half a, __half b) {
    __half2 t(a, b);
    return *reinterpret_cast<unsigned*>(&t);
}

static constexpr int TS = 40;                 // padded smem row stride (fp16)
static constexpr int AT_B = 128 * TS * 2;     // 10240  (128-row tile)
static constexpr int BT_B = 256 * TS * 2;     // 20480  (256-row tile)

// ---------------------------------------------------------------------------
// Plain fp16 GEMM (used for GEMM1): C[M,Ntot] = A[M,K] @ B[Ntot,K]^T, fp16 out.
// CTA 128x256, 8 warps (2m x 4n), BK=32, 3-stage cp.async.
// grid = (Ntot/256, M/128, batch)
// ---------------------------------------------------------------------------
static constexpr int SMEM_G1 = 3 * (AT_B + BT_B);   // 92160

__global__ __launch_bounds__(256, 1) void k_mma_gemm(
    const __half* __restrict__ A0, const __half* __restrict__ B0,
    __half* __restrict__ Ch, int Ntot, int K, size_t sA, size_t sB, size_t sC)
{
    constexpr int O_B0 = AT_B;
    constexpr int STAGE = AT_B + BT_B;

    extern __shared__ __align__(128) char smem[];
    const int tid = threadIdx.x;
    const int wid = tid >> 5, lane = tid & 31;
    const int wm = (wid & 1) * 64, wn = (wid >> 1) * 64;
    const size_t bz = blockIdx.z;
    A0 += bz * sA;
    B0 += bz * sB;
    const int m0 = blockIdx.y * 128, n0 = blockIdx.x * 256;
    const uint32_t sb = smem_u32(smem);

    float acc[4][8][4];
    #pragma unroll
    for (int i = 0; i < 4; i++)
        #pragma unroll
        for (int j = 0; j < 8; j++)
            #pragma unroll
            for (int c = 0; c < 4; c++) acc[i][j][c] = 0.f;

    const int lrow = tid >> 2, lcol = (tid & 3) * 8;
    auto issue = [&](int it, int buf) {
        const int k0 = it << 5;
        const uint32_t s = sb + buf * STAGE;
        #pragma unroll
        for (int r = 0; r < 2; r++) {
            const int row = lrow + r * 64;
            CPA16(s + (uint32_t)(row * TS + lcol) * 2,
                  A0 + (size_t)(m0 + row) * K + k0 + lcol);
        }
        #pragma unroll
        for (int r = 0; r < 4; r++) {
            const int row = lrow + r * 64;
            CPA16(s + O_B0 + (uint32_t)(row * TS + lcol) * 2,
                  B0 + (size_t)(n0 + row) * K + k0 + lcol);
        }
    };

    const int l7 = lane & 7, lb3 = (lane >> 3) & 1, lb4 = lane >> 4;
    const int nch = K >> 5;

    issue(0, 0); CPCOMMIT();
    if (nch > 1) { issue(1, 1); CPCOMMIT(); }

    int buf = 0;
    for (int i = 0; i < nch; i++) {
        if (i + 2 < nch) { issue(i + 2, (buf + 2) % 3); CPCOMMIT(); CPWAIT(2); }
        else if (i + 1 < nch) { CPWAIT(1); }
        else { CPWAIT(0); }
        __syncthreads();

        const uint32_t s = sb + buf * STAGE;
        #pragma unroll
        for (int ks = 0; ks < 2; ks++) {
            const int ko = ks * 16;
            uint32_t af[4][4], bf[8][2];
            #pragma unroll
            for (int mf = 0; mf < 4; mf++) {
                int row = wm + mf * 16 + l7 + lb3 * 8;
                LDSM4(af[mf][0], af[mf][1], af[mf][2], af[mf][3],
                      s + (uint32_t)(row * TS + ko + lb4 * 8) * 2);
            }
            #pragma unroll
            for (int nq = 0; nq < 4; nq++) {
                int nr = wn + nq * 16 + l7 + lb4 * 8;
                LDSM4(bf[nq * 2][0], bf[nq * 2][1], bf[nq * 2 + 1][0], bf[nq * 2 + 1][1],
                      s + O_B0 + (uint32_t)(nr * TS + ko + lb3 * 8) * 2);
            }
            #pragma unroll
            for (int mf = 0; mf < 4; mf++)
                #pragma unroll
                for (int nf = 0; nf < 8; nf++) MMA16816(acc[mf][nf], af[mf], bf[nf]);
        }
        __syncthreads();
        buf = (buf + 1) % 3;
    }

    __half* Hb = Ch + bz * sC;
    const int crow = m0 + wm + (lane >> 2);
    const int ccol = n0 + wn + (lane & 3) * 2;
    #pragma unroll
    for (int mf = 0; mf < 4; mf++)
        #pragma unroll
        for (int nf = 0; nf < 8; nf++) {
            const size_t o0 = (size_t)(crow + mf * 16)     * Ntot + ccol + nf * 8;
            const size_t o1 = (size_t)(crow + mf * 16 + 8) * Ntot + ccol + nf * 8;
            *(unsigned*)(Hb + o0) = packh2(__float2half_rn(acc[mf][nf][0]),
                                           __float2half_rn(acc[mf][nf][1]));
            *(unsigned*)(Hb + o1) = packh2(__float2half_rn(acc[mf][nf][2]),
                                           __float2half_rn(acc[mf][nf][3]));
        }
}

// ---------------------------------------------------------------------------
// Fused softmax + GEMM2:
//   out[b,i,:] = (sum_j p_ij * Wh[b,j,:]) / (sum_j p_ij)
//   p_ij = exp(lrelu(s1_i + s2_j) - shift_i) masked by adj;
//   shift_i = max(0, s1_i + max_j s2_j)  (=> p <= 1, fp16-safe; cancels in div)
// CTA: 128 i-rows x 256 o-cols (full Fout), 64 k-iters of 32 j.
// grid = (Nn/128, Bb)
// ---------------------------------------------------------------------------
static constexpr int O_P     = 3 * BT_B;             // 61440 (after 3 B-stages)
static constexpr int O_SS1   = O_P + 2 * AT_B;       // 81920
static constexpr int O_SHIFT = O_SS1 + 512;
static constexpr int O_ROW   = O_SHIFT + 512;
static constexpr int SMEM_FUSED = O_ROW + 512;       // 83456

__global__ __launch_bounds__(256, 1) void k_fused(
    const float* __restrict__ adj, const __half* __restrict__ wht,
    float* __restrict__ out)
{
    extern __shared__ __align__(128) char smem[];
    const int tid = threadIdx.x;
    const int wid = tid >> 5, lane = tid & 31;
    const int b = blockIdx.y;
    const int m0 = blockIdx.x * 128;
    const uint32_t sb = smem_u32(smem);

    const __half* Bw  = wht + (size_t)b * Ff * Nn;
    const float*  s2p = g_s2 + b * Nn;
    float* ss1    = (float*)(smem + O_SS1);
    float* sshift = (float*)(smem + O_SHIFT);
    float* srow   = (float*)(smem + O_ROW);

    if (tid < 128) {
        float s1v = g_s1[b * Nn + m0 + tid];
        ss1[tid] = s1v;
        sshift[tid] = fmaxf(0.f, s1v + g_m2[b]);
    }

    float acc[4][8][4];
    #pragma unroll
    for (int i = 0; i < 4; i++)
        #pragma unroll
        for (int j = 0; j < 8; j++)
            #pragma unroll
            for (int c = 0; c < 4; c++) acc[i][j][c] = 0.f;
    float rsum = 0.f;

    const int wm = (wid & 1) * 64, wn = (wid >> 1) * 64;
    const int l7 = lane & 7, lb3 = (lane >> 3) & 1, lb4 = lane >> 4;

    // B (WhT) tile loader: 256 rows(o) x 32 cols(j) fp16 per stage
    // 256 rows x 4 chunks of 16B = 1024 chunks; 4 per thread.
    auto issueB = [&](int it, int st) {
        const int j0 = it << 5;
        const uint32_t s = sb + st * BT_B;
        #pragma unroll
        for (int r = 0; r < 4; r++) {
            int u = tid + r * 256;
            int row = u >> 2, c = u & 3;
            CPA16(s + (uint32_t)(row * TS + c * 8) * 2,
                  Bw + (size_t)row * Nn + j0 + c * 8);
        }
    };

    // p-tile mapping: thread -> (row pr, 16-col half pch)
    const int pr = tid >> 1, pch = tid & 1;
    const float* arow = adj + (size_t)(m0 + pr) * Nn;

    issueB(0, 0); CPCOMMIT();
    issueB(1, 1); CPCOMMIT();
    __syncthreads();   // ss1/sshift visible

    for (int it = 0; it < 64; it++) {
        if (it + 2 < 64) { issueB(it + 2, (it + 2) % 3); CPCOMMIT(); CPWAIT(2); }
        else if (it + 1 < 64) { CPWAIT(1); }
        else { CPWAIT(0); }

        // ---- compute p tile (128 x 32) into P[it&1] ----
        {
            const int j0 = (it << 5) + pch * 16;
            const float s1v = ss1[pr], shv = sshift[pr];
            float4 av[4], qv[4];
            #pragma unroll
            for (int t = 0; t < 4; t++) {
                av[t] = *(const float4*)(arow + j0 + 4 * t);
                qv[t] = *(const float4*)(s2p + j0 + 4 * t);
            }
            const float* avf = (const float*)av;
            const float* qvf = (const float*)qv;
            unsigned pk[8];
            #pragma unroll
            for (int k = 0; k < 8; k++) {
                float p2[2];
                #pragma unroll
                for (int u = 0; u < 2; u++) {
                    float t = s1v + qvf[2 * k + u];
                    t = (t >= 0.f) ? t : ALPHA * t;
                    float pv = (avf[2 * k + u] != 0.f) ? __expf(t - shv) : 0.f;
                    p2[u] = pv;
                    rsum += pv;
                }
                pk[k] = packh2(__float2half_rn(p2[0]), __float2half_rn(p2[1]));
            }
            char* dst = smem + O_P + (it & 1) * AT_B + (uint32_t)(pr * TS + pch * 16) * 2;
            *(uint4*)dst        = make_uint4(pk[0], pk[1], pk[2], pk[3]);
            *(uint4*)(dst + 16) = make_uint4(pk[4], pk[5], pk[6], pk[7]);
        }
        __syncthreads();

        // ---- MMA: acc += P_tile @ B_tile^T ----
        const uint32_t sP = sb + O_P + (it & 1) * AT_B;
        const uint32_t sB = sb + (it % 3) * BT_B;
        #pragma unroll
        for (int ks = 0; ks < 2; ks++) {
            const int ko = ks * 16;
            uint32_t af[4][4], bf[8][2];
            #pragma unroll
            for (int mf = 0; mf < 4; mf++) {
                int row = wm + mf * 16 + l7 + lb3 * 8;
                LDSM4(af[mf][0], af[mf][1], af[mf][2], af[mf][3],
                      sP + (uint32_t)(row * TS + ko + lb4 * 8) * 2);
            }
            #pragma unroll
            for (int nq = 0; nq < 4; nq++) {
                int nr = wn + nq * 16 + l7 + lb4 * 8;
                LDSM4(bf[nq * 2][0], bf[nq * 2][1], bf[nq * 2 + 1][0], bf[nq * 2 + 1][1],
                      sB + (uint32_t)(nr * TS + ko + lb3 * 8) * 2);
            }
            #pragma unroll
            for (int mf = 0; mf < 4; mf++)
                #pragma unroll
                for (int nf = 0; nf < 8; nf++) MMA16816(acc[mf][nf], af[mf], bf[nf]);
        }
        __syncthreads();
    }

    // ---- rowsums (each row held by thread pair tid, tid^1) ----
    float tot = rsum + __shfl_xor_sync(0xffffffffu, rsum, 1);
    if (!(tid & 1)) srow[pr] = tot;
    __syncthreads();

    // ---- epilogue: normalize and store fp32 ----
    float* ob = out + (size_t)b * Nn * Ff;
    const int lr0 = wm + (lane >> 2);
    const int ccol = wn + (lane & 3) * 2;
    #pragma unroll
    for (int mf = 0; mf < 4; mf++) {
        const int r0 = lr0 + mf * 16, r1 = r0 + 8;
        const float inv0 = 1.f / srow[r0], inv1 = 1.f / srow[r1];
        #pragma unroll
        for (int nf = 0; nf < 8; nf++) {
            float* p0 = ob + (size_t)(m0 + r0) * Ff + ccol + nf * 8;
            float* p1 = ob + (size_t)(m0 + r1) * Ff + ccol + nf * 8;
            *(float2*)p0 = make_float2(acc[mf][nf][0] * inv0, acc[mf][nf][1] * inv0);
            *(float2*)p1 = make_float2(acc[mf][nf][2] * inv1, acc[mf][nf][3] * inv1);
        }
    }
}

// ---------------------------------------------------------------------------
// Prep W: Wt fp16 (block o transposes col o); block 0 also computes wa1/wa2.
// ---------------------------------------------------------------------------
__global__ void k_prep_w(const float* __restrict__ W, const float* __restrict__ a,
                         __half* __restrict__ T) {
    const int o = blockIdx.x, f = threadIdx.x;
    T[(size_t)o * Ff + f] = __float2half_rn(W[(size_t)f * Ff + o]);
    if (o == 0) {
        float d1 = 0.f, d2 = 0.f;
        const float* wrow = W + (size_t)f * Ff;
        #pragma unroll 8
        for (int j = 0; j < Ff; j++) {
            float w = wrow[j];
            d1 += w * a[j];
            d2 += w * a[Ff + j];
        }
        g_wa[f] = d1;
        g_wa[Ff + f] = d2;
    }
}

// ---------------------------------------------------------------------------
// Prep h: fp16 conversion + s1/s2 dots (reads h exactly once). Warp per row.
// ---------------------------------------------------------------------------
__global__ __launch_bounds__(256) void k_prep_h(const float* __restrict__ h,
                                                __half* __restrict__ hf) {
    __shared__ float swa[2 * Ff];
    for (int i = threadIdx.x; i < 2 * Ff; i += 256) swa[i] = g_wa[i];
    __syncthreads();

    const int warp = threadIdx.x >> 5, lane = threadIdx.x & 31;
    const int row = blockIdx.x * 8 + warp;
    const float* hp = h + (size_t)row * Ff;
    const int j0 = lane * 8;

    float4 v0 = *(const float4*)(hp + j0), v1 = *(const float4*)(hp + j0 + 4);
    float v[8] = {v0.x, v0.y, v0.z, v0.w, v1.x, v1.y, v1.z, v1.w};

    unsigned pk[4];
    #pragma unroll
    for (int k = 0; k < 4; k++)
        pk[k] = packh2(__float2half_rn(v[2 * k]), __float2half_rn(v[2 * k + 1]));
    *(uint4*)(hf + (size_t)row * Ff + j0) = make_uint4(pk[0], pk[1], pk[2], pk[3]);

    float d1 = 0.f, d2 = 0.f;
    #pragma unroll
    for (int k = 0; k < 8; k++) {
        d1 += v[k] * swa[j0 + k];
        d2 += v[k] * swa[Ff + j0 + k];
    }
    #pragma unroll
    for (int off = 16; off; off >>= 1) {
        d1 += __shfl_xor_sync(0xffffffffu, d1, off);
        d2 += __shfl_xor_sync(0xffffffffu, d2, off);
    }
    if (lane == 0) { g_s1[row] = d1; g_s2[row] = d2; }
}

// ---------------------------------------------------------------------------
// Per-batch max of s2 -> g_m2[b]
// ---------------------------------------------------------------------------
__global__ __launch_bounds__(256) void k_s2max() {
    const int b = blockIdx.x;
    __shared__ float sred[8];
    const float* s2p = g_s2 + b * Nn;
    float m = -INFINITY;
    for (int j = threadIdx.x; j < Nn; j += 256) m = fmaxf(m, s2p[j]);
    #pragma unroll
    for (int off = 16; off; off >>= 1) m = fmaxf(m, __shfl_xor_sync(0xffffffffu, m, off));
    const int warp = threadIdx.x >> 5, lane = threadIdx.x & 31;
    if (lane == 0) sred[warp] = m;
    __syncthreads();
    if (warp == 0) {
        float v = (lane < 8) ? sred[lane] : -INFINITY;
        #pragma unroll
        for (int off = 4; off; off >>= 1) v = fmaxf(v, __shfl_xor_sync(0xffffffffu, v, off));
        if (lane == 0) g_m2[b] = v;
    }
}

// ---------------------------------------------------------------------------
// Launch
// ---------------------------------------------------------------------------
extern "C" void kernel_launch(void* const* d_in, const int* in_sizes, int n_in,
                              void* d_out, int out_size) {
    const float* h   = (const float*)d_in[0];  // [8, 2048, 256]
    const float* adj = (const float*)d_in[1];  // [2048, 2048]
    const float* W   = (const float*)d_in[2];  // [256, 256]
    const float* a   = (const float*)d_in[3];  // [512, 1]
    float* out = (float*)d_out;                // [8, 2048, 256]

    __half *hf, *wt, *wht;
    cudaGetSymbolAddress((void**)&hf,  g_hf);
    cudaGetSymbolAddress((void**)&wt,  g_wt);
    cudaGetSymbolAddress((void**)&wht, g_wht);

    cudaFuncSetAttribute(k_mma_gemm, cudaFuncAttributeMaxDynamicSharedMemorySize, SMEM_G1);
    cudaFuncSetAttribute(k_fused,    cudaFuncAttributeMaxDynamicSharedMemorySize, SMEM_FUSED);

    k_prep_w<<<Ff, Ff>>>(W, a, wt);
    k_prep_h<<<(Bb * Nn) / 8, 256>>>(h, hf);
    k_s2max<<<Bb, 256>>>();

    // GEMM1 (fused transpose): WhT[b][o][n] = sum_f Wt[o,f] * h[b,n,f]
    k_mma_gemm<<<dim3(Nn / 256, Ff / 128, Bb), 256, SMEM_G1>>>(
        wt, hf, wht, Nn, Ff, 0, (size_t)Nn * Ff, (size_t)Ff * Nn);

    // Fused softmax + GEMM2
    k_fused<<<dim3(Nn / 128, Bb), 256, SMEM_FUSED>>>(adj, wht, out);
}

// round 9
// speedup vs baseline: 1.0563x; 1.0563x over previous
#include <cuda_runtime.h>
#include <cuda_fp16.h>
#include <math.h>
#include <stdint.h>

#define ALPHA 0.2f

static constexpr int Bb = 8;     // batch
static constexpr int Nn = 2048;  // nodes
static constexpr int Ff = 256;   // features (Fin == Fout)

// ---------------------------------------------------------------------------
// Scratch (__device__ globals: allocation-free rule)
// ---------------------------------------------------------------------------
__device__ __align__(1024) __half g_hf[(size_t)Bb * Nn * Ff];     // h as fp16
__device__ __align__(1024) __half g_wt[Ff * Ff];                  // W^T fp16
__device__ __align__(1024) __half g_wht[(size_t)Bb * Ff * Nn];    // WhT fp16
__device__ __align__(16)   float g_s1[Bb * Nn];
__device__ __align__(16)   float g_s2[Bb * Nn];
__device__ __align__(16)   float g_wa[2 * Ff];
__device__ __align__(16)   float g_m2[Bb];                        // max_j s2[b,j]

// ---------------------------------------------------------------------------
// Helpers (baseline PTX only: mma.sync / ldmatrix / cp.async)
// ---------------------------------------------------------------------------
__device__ __forceinline__ uint32_t smem_u32(const void* p) {
    uint32_t a;
    asm("{ .reg .u64 t; cvta.to.shared.u64 t, %1; cvt.u32.u64 %0, t; }" : "=r"(a) : "l"(p));
    return a;
}
#define LDSM4(r0, r1, r2, r3, addr) \
    asm volatile("ldmatrix.sync.aligned.m8n8.x4.shared.b16 {%0,%1,%2,%3}, [%4];" \
                 : "=r"(r0), "=r"(r1), "=r"(r2), "=r"(r3) : "r"(addr))
#define MMA16816(d, a, b) \
    asm volatile("mma.sync.aligned.m16n8k16.row.col.f32.f16.f16.f32 " \
                 "{%0,%1,%2,%3},{%4,%5,%6,%7},{%8,%9},{%0,%1,%2,%3};" \
                 : "+f"((d)[0]), "+f"((d)[1]), "+f"((d)[2]), "+f"((d)[3]) \
                 : "r"((a)[0]), "r"((a)[1]), "r"((a)[2]), "r"((a)[3]), \
                   "r"((b)[0]), "r"((b)[1]))
#define CPA16(s, g) asm volatile("cp.async.cg.shared.global [%0], [%1], 16;" :: "r"(s), "l"(g))
#define CPCOMMIT()  asm volatile("cp.async.commit_group;" ::: "memory")
#define CPWAIT(n)   asm volatile("cp.async.wait_group %0;" :: "n"(n) : "memory")

__device__ __forceinline__ unsigned packh2(__half a, __half b) {
    __half2 t(a, b);
    return *reinterpret_cast<unsigned*>(&t);
}

static constexpr int TS = 40;                 // padded smem row stride (fp16)
static constexpr int AT_B = 128 * TS * 2;     // 10240  (128-row tile)
static constexpr int BT_B = 256 * TS * 2;     // 20480  (256-row tile)

// ---------------------------------------------------------------------------
// Plain fp16 GEMM (used for GEMM1): C[M,Ntot] = A[M,K] @ B[Ntot,K]^T, fp16 out.
// ---------------------------------------------------------------------------
static constexpr int SMEM_G1 = 3 * (AT_B + BT_B);   // 92160

__global__ __launch_bounds__(256, 1) void k_mma_gemm(
    const __half* __restrict__ A0, const __half* __restrict__ B0,
    __half* __restrict__ Ch, int Ntot, int K, size_t sA, size_t sB, size_t sC)
{
    constexpr int O_B0 = AT_B;
    constexpr int STAGE = AT_B + BT_B;

    extern __shared__ __align__(128) char smem[];
    const int tid = threadIdx.x;
    const int wid = tid >> 5, lane = tid & 31;
    const int wm = (wid & 1) * 64, wn = (wid >> 1) * 64;
    const size_t bz = blockIdx.z;
    A0 += bz * sA;
    B0 += bz * sB;
    const int m0 = blockIdx.y * 128, n0 = blockIdx.x * 256;
    const uint32_t sb = smem_u32(smem);

    float acc[4][8][4];
    #pragma unroll
    for (int i = 0; i < 4; i++)
        #pragma unroll
        for (int j = 0; j < 8; j++)
            #pragma unroll
            for (int c = 0; c < 4; c++) acc[i][j][c] = 0.f;

    const int lrow = tid >> 2, lcol = (tid & 3) * 8;
    auto issue = [&](int it, int buf) {
        const int k0 = it << 5;
        const uint32_t s = sb + buf * STAGE;
        #pragma unroll
        for (int r = 0; r < 2; r++) {
            const int row = lrow + r * 64;
            CPA16(s + (uint32_t)(row * TS + lcol) * 2,
                  A0 + (size_t)(m0 + row) * K + k0 + lcol);
        }
        #pragma unroll
        for (int r = 0; r < 4; r++) {
            const int row = lrow + r * 64;
            CPA16(s + O_B0 + (uint32_t)(row * TS + lcol) * 2,
                  B0 + (size_t)(n0 + row) * K + k0 + lcol);
        }
    };

    const int l7 = lane & 7, lb3 = (lane >> 3) & 1, lb4 = lane >> 4;
    const int nch = K >> 5;

    issue(0, 0); CPCOMMIT();
    if (nch > 1) { issue(1, 1); CPCOMMIT(); }

    int buf = 0;
    for (int i = 0; i < nch; i++) {
        if (i + 2 < nch) { issue(i + 2, (buf + 2) % 3); CPCOMMIT(); CPWAIT(2); }
        else if (i + 1 < nch) { CPWAIT(1); }
        else { CPWAIT(0); }
        __syncthreads();

        const uint32_t s = sb + buf * STAGE;
        #pragma unroll
        for (int ks = 0; ks < 2; ks++) {
            const int ko = ks * 16;
            uint32_t af[4][4], bf[8][2];
            #pragma unroll
            for (int mf = 0; mf < 4; mf++) {
                int row = wm + mf * 16 + l7 + lb3 * 8;
                LDSM4(af[mf][0], af[mf][1], af[mf][2], af[mf][3],
                      s + (uint32_t)(row * TS + ko + lb4 * 8) * 2);
            }
            #pragma unroll
            for (int nq = 0; nq < 4; nq++) {
                int nr = wn + nq * 16 + l7 + lb4 * 8;
                LDSM4(bf[nq * 2][0], bf[nq * 2][1], bf[nq * 2 + 1][0], bf[nq * 2 + 1][1],
                      s + O_B0 + (uint32_t)(nr * TS + ko + lb3 * 8) * 2);
            }
            #pragma unroll
            for (int mf = 0; mf < 4; mf++)
                #pragma unroll
                for (int nf = 0; nf < 8; nf++) MMA16816(acc[mf][nf], af[mf], bf[nf]);
        }
        __syncthreads();
        buf = (buf + 1) % 3;
    }

    __half* Hb = Ch + bz * sC;
    const int crow = m0 + wm + (lane >> 2);
    const int ccol = n0 + wn + (lane & 3) * 2;
    #pragma unroll
    for (int mf = 0; mf < 4; mf++)
        #pragma unroll
        for (int nf = 0; nf < 8; nf++) {
            const size_t o0 = (size_t)(crow + mf * 16)     * Ntot + ccol + nf * 8;
            const size_t o1 = (size_t)(crow + mf * 16 + 8) * Ntot + ccol + nf * 8;
            *(unsigned*)(Hb + o0) = packh2(__float2half_rn(acc[mf][nf][0]),
                                           __float2half_rn(acc[mf][nf][1]));
            *(unsigned*)(Hb + o1) = packh2(__float2half_rn(acc[mf][nf][2]),
                                           __float2half_rn(acc[mf][nf][3]));
        }
}

// ---------------------------------------------------------------------------
// Fused softmax + GEMM2 (pipelined):
//   out[b,i,:] = (sum_j p_ij * Wh[b,j,:]) / (sum_j p_ij)
//   p_ij = exp(lrelu(s1_i + s2_j) - shift_i) masked by adj; shift cancels.
// adj tiles AND WhT tiles both ride a 3-stage cp.async pipeline; s2 lives in
// SMEM; the p-tile for it+1 is computed AFTER the MMA of it (all-SMEM reads),
// so no global latency is ever exposed inside the loop.
// CTA: 128 i-rows x 256 o-cols, 64 iters of 32 j.  grid = (Nn/128, Bb)
// ---------------------------------------------------------------------------
static constexpr int ADJ_TS = 36;                     // padded fp32 row stride
static constexpr int ADJ_B  = 128 * ADJ_TS * 4;       // 18432 per stage
static constexpr int O_P    = 3 * BT_B;               // 61440
static constexpr int O_ADJ  = O_P + 2 * AT_B;         // 81920
static constexpr int O_S2   = O_ADJ + 3 * ADJ_B;      // 137216
static constexpr int O_SS1  = O_S2 + Nn * 4;          // 145408
static constexpr int O_SHIFT = O_SS1 + 512;
static constexpr int O_ROW   = O_SHIFT + 512;
static constexpr int SMEM_FUSED = O_ROW + 512;        // 146944

__global__ __launch_bounds__(256, 1) void k_fused(
    const float* __restrict__ adj, const __half* __restrict__ wht,
    float* __restrict__ out)
{
    extern __shared__ __align__(128) char smem[];
    const int tid = threadIdx.x;
    const int wid = tid >> 5, lane = tid & 31;
    const int b = blockIdx.y;
    const int m0 = blockIdx.x * 128;
    const uint32_t sb = smem_u32(smem);

    const __half* Bw  = wht + (size_t)b * Ff * Nn;
    const float*  s2p = g_s2 + b * Nn;
    float* ss2    = (float*)(smem + O_S2);
    float* ss1    = (float*)(smem + O_SS1);
    float* sshift = (float*)(smem + O_SHIFT);
    float* srow   = (float*)(smem + O_ROW);

    // preload s2 (8 KB) + ss1/shift
    #pragma unroll
    for (int r = 0; r < 2; r++) {
        int u = tid + r * 256;
        ((float4*)ss2)[u] = ((const float4*)s2p)[u];
    }
    if (tid < 128) {
        float s1v = g_s1[b * Nn + m0 + tid];
        ss1[tid] = s1v;
        sshift[tid] = fmaxf(0.f, s1v + g_m2[b]);
    }

    float acc[4][8][4];
    #pragma unroll
    for (int i = 0; i < 4; i++)
        #pragma unroll
        for (int j = 0; j < 8; j++)
            #pragma unroll
            for (int c = 0; c < 4; c++) acc[i][j][c] = 0.f;
    float rsum = 0.f;

    const int wm = (wid & 1) * 64, wn = (wid >> 1) * 64;
    const int l7 = lane & 7, lb3 = (lane >> 3) & 1, lb4 = lane >> 4;

    // One commit group per stage: B tile (WhT 256rows x 32j fp16) + adj tile
    // (128rows x 32j fp32).
    auto issueAll = [&](int it, int st) {
        const int j0 = it << 5;
        const uint32_t sB = sb + st * BT_B;
        #pragma unroll
        for (int r = 0; r < 4; r++) {
            int u = tid + r * 256;
            int row = u >> 2, c = u & 3;
            CPA16(sB + (uint32_t)(row * TS + c * 8) * 2,
                  Bw + (size_t)row * Nn + j0 + c * 8);
        }
        const uint32_t sA = sb + O_ADJ + st * ADJ_B;
        #pragma unroll
        for (int r = 0; r < 4; r++) {
            int u = tid + r * 256;
            int row = u >> 3, c = u & 7;
            CPA16(sA + (uint32_t)(row * ADJ_TS + c * 4) * 4,
                  adj + (size_t)(m0 + row) * Nn + j0 + c * 4);
        }
    };

    // p-tile mapping: thread -> (row pr, 16-col half pch)
    const int pr = tid >> 1, pch = tid & 1;

    // compute P[it] from SMEM adj stage (it%3) + s2 + ss1
    auto computeP = [&](int it) {
        const int jb = pch * 16;               // within-tile col base
        const float s1v = ss1[pr], shv = sshift[pr];
        const float* arow = (const float*)(smem + O_ADJ + (it % 3) * ADJ_B) + pr * ADJ_TS;
        const float* s2b  = ss2 + (it << 5);
        unsigned pk[8];
        #pragma unroll
        for (int k = 0; k < 8; k++) {
            float p2[2];
            #pragma unroll
            for (int u = 0; u < 2; u++) {
                const int j = jb + 2 * k + u;
                float t = s1v + s2b[j];
                t = (t >= 0.f) ? t : ALPHA * t;
                float pv = (arow[j] != 0.f) ? __expf(t - shv) : 0.f;
                p2[u] = pv;
                rsum += pv;
            }
            pk[k] = packh2(__float2half_rn(p2[0]), __float2half_rn(p2[1]));
        }
        char* dst = smem + O_P + (it & 1) * AT_B + (uint32_t)(pr * TS + jb) * 2;
        *(uint4*)dst        = make_uint4(pk[0], pk[1], pk[2], pk[3]);
        *(uint4*)(dst + 16) = make_uint4(pk[4], pk[5], pk[6], pk[7]);
    };

    issueAll(0, 0); CPCOMMIT();
    issueAll(1, 1); CPCOMMIT();
    CPWAIT(1);           // stage 0 landed
    __syncthreads();     // + ss1/ss2 visible
    computeP(0);
    __syncthreads();

    for (int it = 0; it < 64; it++) {
        if (it + 2 < 64) { issueAll(it + 2, (it + 2) % 3); CPCOMMIT(); CPWAIT(1); }
        else             { CPWAIT(0); }

        // ---- MMA: acc += P[it] @ B[it]^T  (hides cp.async flight) ----
        const uint32_t sP = sb + O_P + (it & 1) * AT_B;
        const uint32_t sB = sb + (it % 3) * BT_B;
        #pragma unroll
        for (int ks = 0; ks < 2; ks++) {
            const int ko = ks * 16;
            uint32_t af[4][4], bf[8][2];
            #pragma unroll
            for (int mf = 0; mf < 4; mf++) {
                int row = wm + mf * 16 + l7 + lb3 * 8;
                LDSM4(af[mf][0], af[mf][1], af[mf][2], af[mf][3],
                      sP + (uint32_t)(row * TS + ko + lb4 * 8) * 2);
            }
            #pragma unroll
            for (int nq = 0; nq < 4; nq++) {
                int nr = wn + nq * 16 + l7 + lb4 * 8;
                LDSM4(bf[nq * 2][0], bf[nq * 2][1], bf[nq * 2 + 1][0], bf[nq * 2 + 1][1],
                      sB + (uint32_t)(nr * TS + ko + lb3 * 8) * 2);
            }
            #pragma unroll
            for (int mf = 0; mf < 4; mf++)
                #pragma unroll
                for (int nf = 0; nf < 8; nf++) MMA16816(acc[mf][nf], af[mf], bf[nf]);
        }

        // ---- compute P[it+1] into the other buffer (all-SMEM reads) ----
        if (it + 1 < 64) computeP(it + 1);
        __syncthreads();
    }

    // ---- rowsums (each row held by thread pair tid, tid^1) ----
    float tot = rsum + __shfl_xor_sync(0xffffffffu, rsum, 1);
    if (!(tid & 1)) srow[pr] = tot;
    __syncthreads();

    // ---- epilogue: normalize and store fp32 ----
    float* ob = out + (size_t)b * Nn * Ff;
    const int lr0 = wm + (lane >> 2);
    const int ccol = wn + (lane & 3) * 2;
    #pragma unroll
    for (int mf = 0; mf < 4; mf++) {
        const int r0 = lr0 + mf * 16, r1 = r0 + 8;
        const float inv0 = 1.f / srow[r0], inv1 = 1.f / srow[r1];
        #pragma unroll
        for (int nf = 0; nf < 8; nf++) {
            float* p0 = ob + (size_t)(m0 + r0) * Ff + ccol + nf * 8;
            float* p1 = ob + (size_t)(m0 + r1) * Ff + ccol + nf * 8;
            *(float2*)p0 = make_float2(acc[mf][nf][0] * inv0, acc[mf][nf][1] * inv0);
            *(float2*)p1 = make_float2(acc[mf][nf][2] * inv1, acc[mf][nf][3] * inv1);
        }
    }
}

// ---------------------------------------------------------------------------
// Prep W: Wt fp16 (block o transposes col o); block 0 also computes wa1/wa2.
// ---------------------------------------------------------------------------
__global__ void k_prep_w(const float* __restrict__ W, const float* __restrict__ a,
                         __half* __restrict__ T) {
    const int o = blockIdx.x, f = threadIdx.x;
    T[(size_t)o * Ff + f] = __float2half_rn(W[(size_t)f * Ff + o]);
    if (o == 0) {
        float d1 = 0.f, d2 = 0.f;
        const float* wrow = W + (size_t)f * Ff;
        #pragma unroll 8
        for (int j = 0; j < Ff; j++) {
            float w = wrow[j];
            d1 += w * a[j];
            d2 += w * a[Ff + j];
        }
        g_wa[f] = d1;
        g_wa[Ff + f] = d2;
    }
}

// ---------------------------------------------------------------------------
// Prep h: fp16 conversion + s1/s2 dots (reads h exactly once). Warp per row.
// ---------------------------------------------------------------------------
__global__ __launch_bounds__(256) void k_prep_h(const float* __restrict__ h,
                                                __half* __restrict__ hf) {
    __shared__ float swa[2 * Ff];
    for (int i = threadIdx.x; i < 2 * Ff; i += 256) swa[i] = g_wa[i];
    __syncthreads();

    const int warp = threadIdx.x >> 5, lane = threadIdx.x & 31;
    const int row = blockIdx.x * 8 + warp;
    const float* hp = h + (size_t)row * Ff;
    const int j0 = lane * 8;

    float4 v0 = *(const float4*)(hp + j0), v1 = *(const float4*)(hp + j0 + 4);
    float v[8] = {v0.x, v0.y, v0.z, v0.w, v1.x, v1.y, v1.z, v1.w};

    unsigned pk[4];
    #pragma unroll
    for (int k = 0; k < 4; k++)
        pk[k] = packh2(__float2half_rn(v[2 * k]), __float2half_rn(v[2 * k + 1]));
    *(uint4*)(hf + (size_t)row * Ff + j0) = make_uint4(pk[0], pk[1], pk[2], pk[3]);

    float d1 = 0.f, d2 = 0.f;
    #pragma unroll
    for (int k = 0; k < 8; k++) {
        d1 += v[k] * swa[j0 + k];
        d2 += v[k] * swa[Ff + j0 + k];
    }
    #pragma unroll
    for (int off = 16; off; off >>= 1) {
        d1 += __shfl_xor_sync(0xffffffffu, d1, off);
        d2 += __shfl_xor_sync(0xffffffffu, d2, off);
    }
    if (lane == 0) { g_s1[row] = d1; g_s2[row] = d2; }
}

// ---------------------------------------------------------------------------
// Per-batch max of s2 -> g_m2[b]
// ---------------------------------------------------------------------------
__global__ __launch_bounds__(256) void k_s2max() {
    const int b = blockIdx.x;
    __shared__ float sred[8];
    const float* s2p = g_s2 + b * Nn;
    float m = -INFINITY;
    for (int j = threadIdx.x; j < Nn; j += 256) m = fmaxf(m, s2p[j]);
    #pragma unroll
    for (int off = 16; off; off >>= 1) m = fmaxf(m, __shfl_xor_sync(0xffffffffu, m, off));
    const int warp = threadIdx.x >> 5, lane = threadIdx.x & 31;
    if (lane == 0) sred[warp] = m;
    __syncthreads();
    if (warp == 0) {
        float v = (lane < 8) ? sred[lane] : -INFINITY;
        #pragma unroll
        for (int off = 4; off; off >>= 1) v = fmaxf(v, __shfl_xor_sync(0xffffffffu, v, off));
        if (lane == 0) g_m2[b] = v;
    }
}

// ---------------------------------------------------------------------------
// Launch
// ---------------------------------------------------------------------------
extern "C" void kernel_launch(void* const* d_in, const int* in_sizes, int n_in,
                              void* d_out, int out_size) {
    const float* h   = (const float*)d_in[0];  // [8, 2048, 256]
    const float* adj = (const float*)d_in[1];  // [2048, 2048]
    const float* W   = (const float*)d_in[2];  // [256, 256]
    const float* a   = (const float*)d_in[3];  // [512, 1]
    float* out = (float*)d_out;                // [8, 2048, 256]

    __half *hf, *wt, *wht;
    cudaGetSymbolAddress((void**)&hf,  g_hf);
    cudaGetSymbolAddress((void**)&wt,  g_wt);
    cudaGetSymbolAddress((void**)&wht, g_wht);

    cudaFuncSetAttribute(k_mma_gemm, cudaFuncAttributeMaxDynamicSharedMemorySize, SMEM_G1);
    cudaFuncSetAttribute(k_fused,    cudaFuncAttributeMaxDynamicSharedMemorySize, SMEM_FUSED);

    k_prep_w<<<Ff, Ff>>>(W, a, wt);
    k_prep_h<<<(Bb * Nn) / 8, 256>>>(h, hf);
    k_s2max<<<Bb, 256>>>();

    // GEMM1 (fused transpose): WhT[b][o][n] = sum_f Wt[o,f] * h[b,n,f]
    k_mma_gemm<<<dim3(Nn / 256, Ff / 128, Bb), 256, SMEM_G1>>>(
        wt, hf, wht, Nn, Ff, 0, (size_t)Nn * Ff, (size_t)Ff * Nn);

    // Fused softmax + GEMM2 (pipelined)
    k_fused<<<dim3(Nn / 128, Bb), 256, SMEM_FUSED>>>(adj, wht, out);
}

// round 10
// speedup vs baseline: 1.4336x; 1.3572x over previous
#include <cuda_runtime.h>
#include <cuda_fp16.h>
#include <math.h>
#include <stdint.h>

#define ALPHA 0.2f

static constexpr int Bb = 8;     // batch
static constexpr int Nn = 2048;  // nodes
static constexpr int Ff = 256;   // features (Fin == Fout)

// ---------------------------------------------------------------------------
// Scratch (__device__ globals: allocation-free rule)
// ---------------------------------------------------------------------------
__device__ __align__(1024) __half g_hf[(size_t)Bb * Nn * Ff];     // h as fp16
__device__ __align__(1024) __half g_wt[Ff * Ff];                  // W^T fp16
__device__ __align__(1024) __half g_wht[(size_t)Bb * Ff * Nn];    // WhT fp16
__device__ __align__(1024) __half g_at[(size_t)Bb * Nn * Nn];     // attn fp16 (67 MB)
__device__ __align__(16)   float g_s1[Bb * Nn];
__device__ __align__(16)   float g_s2[Bb * Nn];
__device__ __align__(16)   float g_wa[2 * Ff];

// ---------------------------------------------------------------------------
// Helpers (baseline PTX only: mma.sync / ldmatrix / cp.async)
// ---------------------------------------------------------------------------
__device__ __forceinline__ uint32_t smem_u32(const void* p) {
    uint32_t a;
    asm("{ .reg .u64 t; cvta.to.shared.u64 t, %1; cvt.u32.u64 %0, t; }" : "=r"(a) : "l"(p));
    return a;
}
#define LDSM4(r0, r1, r2, r3, addr) \
    asm volatile("ldmatrix.sync.aligned.m8n8.x4.shared.b16 {%0,%1,%2,%3}, [%4];" \
                 : "=r"(r0), "=r"(r1), "=r"(r2), "=r"(r3) : "r"(addr))
#define MMA16816(d, a, b) \
    asm volatile("mma.sync.aligned.m16n8k16.row.col.f32.f16.f16.f32 " \
                 "{%0,%1,%2,%3},{%4,%5,%6,%7},{%8,%9},{%0,%1,%2,%3};" \
                 : "+f"((d)[0]), "+f"((d)[1]), "+f"((d)[2]), "+f"((d)[3]) \
                 : "r"((a)[0]), "r"((a)[1]), "r"((a)[2]), "r"((a)[3]), \
                   "r"((b)[0]), "r"((b)[1]))
#define CPA16(s, g) asm volatile("cp.async.cg.shared.global [%0], [%1], 16;" :: "r"(s), "l"(g))
#define CPCOMMIT()  asm volatile("cp.async.commit_group;" ::: "memory")
#define CPWAIT(n)   asm volatile("cp.async.wait_group %0;" :: "n"(n) : "memory")

__device__ __forceinline__ unsigned packh2(__half a, __half b) {
    __half2 t(a, b);
    return *reinterpret_cast<unsigned*>(&t);
}

static constexpr int TS = 40;                 // padded smem row stride (fp16), 80B = 16B-aligned
static constexpr int TILE_B = 128 * TS * 2;   // 10240 per 128-row tile
static constexpr int STAGE  = 2 * TILE_B;     // A + B per stage
static constexpr int SMEM_G = 3 * STAGE;      // 61440

// ---------------------------------------------------------------------------
// fp16 GEMM, occupancy-tuned: C[M,Ntot] = A[M,K] @ B[Ntot,K]^T (K-major both)
// CTA 128x128, 8 warps (4m x 2n), warp tile 32x64, acc=64 regs -> 2 CTAs/SM.
// BK=32, 3-stage cp.async.  grid = (Ntot/128, M/128, batch)
// EPI=0: fp32 C.   EPI=1: fp16 Ch.
// ---------------------------------------------------------------------------
template<int EPI>
__global__ __launch_bounds__(256, 2) void k_mma_gemm(
    const __half* __restrict__ A0, const __half* __restrict__ B0,
    float* __restrict__ C, __half* __restrict__ Ch,
    int Ntot, int K, size_t sA, size_t sB, size_t sC)
{
    extern __shared__ __align__(128) char smem[];
    const int tid = threadIdx.x;
    const int wid = tid >> 5, lane = tid & 31;
    const int wm = (wid & 3) * 32;        // 4 m-warps
    const int wn = (wid >> 2) * 64;       // 2 n-warps
    const size_t bz = blockIdx.z;
    A0 += bz * sA;
    B0 += bz * sB;
    const int m0 = blockIdx.y * 128, n0 = blockIdx.x * 128;
    const uint32_t sb = smem_u32(smem);

    float acc[2][8][4];
    #pragma unroll
    for (int i = 0; i < 2; i++)
        #pragma unroll
        for (int j = 0; j < 8; j++)
            #pragma unroll
            for (int c = 0; c < 4; c++) acc[i][j][c] = 0.f;

    // loaders: each tile 128 rows x 4 chunks(16B) = 512 chunks; 2/thread
    const int lrow = tid >> 2, lcol = (tid & 3) * 8;
    auto issue = [&](int it, int buf) {
        const int k0 = it << 5;
        const uint32_t s = sb + buf * STAGE;
        #pragma unroll
        for (int r = 0; r < 2; r++) {
            const int row = lrow + r * 64;
            const uint32_t so = (uint32_t)(row * TS + lcol) * 2;
            CPA16(s + so,          A0 + (size_t)(m0 + row) * K + k0 + lcol);
            CPA16(s + TILE_B + so, B0 + (size_t)(n0 + row) * K + k0 + lcol);
        }
    };

    const int l7 = lane & 7, lb3 = (lane >> 3) & 1, lb4 = lane >> 4;
    const int nch = K >> 5;

    issue(0, 0); CPCOMMIT();
    if (nch > 1) { issue(1, 1); CPCOMMIT(); }

    int buf = 0;
    for (int i = 0; i < nch; i++) {
        if (i + 2 < nch) { issue(i + 2, (buf + 2) % 3); CPCOMMIT(); CPWAIT(2); }
        else if (i + 1 < nch) { CPWAIT(1); }
        else { CPWAIT(0); }
        __syncthreads();

        const uint32_t s = sb + buf * STAGE;
        #pragma unroll
        for (int ks = 0; ks < 2; ks++) {
            const int ko = ks * 16;
            uint32_t af[2][4], bf[8][2];
            #pragma unroll
            for (int mf = 0; mf < 2; mf++) {
                int row = wm + mf * 16 + l7 + lb3 * 8;
                LDSM4(af[mf][0], af[mf][1], af[mf][2], af[mf][3],
                      s + (uint32_t)(row * TS + ko + lb4 * 8) * 2);
            }
            #pragma unroll
            for (int nq = 0; nq < 4; nq++) {
                int nr = wn + nq * 16 + l7 + lb4 * 8;
                LDSM4(bf[nq * 2][0], bf[nq * 2][1], bf[nq * 2 + 1][0], bf[nq * 2 + 1][1],
                      s + TILE_B + (uint32_t)(nr * TS + ko + lb3 * 8) * 2);
            }
            #pragma unroll
            for (int mf = 0; mf < 2; mf++)
                #pragma unroll
                for (int nf = 0; nf < 8; nf++) MMA16816(acc[mf][nf], af[mf], bf[nf]);
        }
        __syncthreads();
        buf = (buf + 1) % 3;
    }

    const int crow = m0 + wm + (lane >> 2);
    const int ccol = n0 + wn + (lane & 3) * 2;
    if (EPI == 0) {
        float* Cb = C + bz * sC;
        #pragma unroll
        for (int mf = 0; mf < 2; mf++)
            #pragma unroll
            for (int nf = 0; nf < 8; nf++) {
                float* p0 = Cb + (size_t)(crow + mf * 16)     * Ntot + ccol + nf * 8;
                float* p1 = Cb + (size_t)(crow + mf * 16 + 8) * Ntot + ccol + nf * 8;
                *(float2*)p0 = make_float2(acc[mf][nf][0], acc[mf][nf][1]);
                *(float2*)p1 = make_float2(acc[mf][nf][2], acc[mf][nf][3]);
            }
    } else {
        __half* Hb = Ch + bz * sC;
        #pragma unroll
        for (int mf = 0; mf < 2; mf++)
            #pragma unroll
            for (int nf = 0; nf < 8; nf++) {
                const size_t o0 = (size_t)(crow + mf * 16)     * Ntot + ccol + nf * 8;
                const size_t o1 = (size_t)(crow + mf * 16 + 8) * Ntot + ccol + nf * 8;
                *(unsigned*)(Hb + o0) = packh2(__float2half_rn(acc[mf][nf][0]),
                                               __float2half_rn(acc[mf][nf][1]));
                *(unsigned*)(Hb + o1) = packh2(__float2half_rn(acc[mf][nf][2]),
                                               __float2half_rn(acc[mf][nf][3]));
            }
    }
}

// ---------------------------------------------------------------------------
// Prep W: Wt fp16 (block o transposes col o); block 0 also computes wa1/wa2.
// ---------------------------------------------------------------------------
__global__ void k_prep_w(const float* __restrict__ W, const float* __restrict__ a,
                         __half* __restrict__ T) {
    const int o = blockIdx.x, f = threadIdx.x;
    T[(size_t)o * Ff + f] = __float2half_rn(W[(size_t)f * Ff + o]);
    if (o == 0) {
        float d1 = 0.f, d2 = 0.f;
        const float* wrow = W + (size_t)f * Ff;
        #pragma unroll 8
        for (int j = 0; j < Ff; j++) {
            float w = wrow[j];
            d1 += w * a[j];
            d2 += w * a[Ff + j];
        }
        g_wa[f] = d1;
        g_wa[Ff + f] = d2;
    }
}

// ---------------------------------------------------------------------------
// Prep h: fp16 conversion + s1/s2 dots (reads h exactly once). Warp per row.
// ---------------------------------------------------------------------------
__global__ __launch_bounds__(256) void k_prep_h(const float* __restrict__ h,
                                                __half* __restrict__ hf) {
    __shared__ float swa[2 * Ff];
    for (int i = threadIdx.x; i < 2 * Ff; i += 256) swa[i] = g_wa[i];
    __syncthreads();

    const int warp = threadIdx.x >> 5, lane = threadIdx.x & 31;
    const int row = blockIdx.x * 8 + warp;
    const float* hp = h + (size_t)row * Ff;
    const int j0 = lane * 8;

    float4 v0 = *(const float4*)(hp + j0), v1 = *(const float4*)(hp + j0 + 4);
    float v[8] = {v0.x, v0.y, v0.z, v0.w, v1.x, v1.y, v1.z, v1.w};

    unsigned pk[4];
    #pragma unroll
    for (int k = 0; k < 4; k++)
        pk[k] = packh2(__float2half_rn(v[2 * k]), __float2half_rn(v[2 * k + 1]));
    *(uint4*)(hf + (size_t)row * Ff + j0) = make_uint4(pk[0], pk[1], pk[2], pk[3]);

    float d1 = 0.f, d2 = 0.f;
    #pragma unroll
    for (int k = 0; k < 8; k++) {
        d1 += v[k] * swa[j0 + k];
        d2 += v[k] * swa[Ff + j0 + k];
    }
    #pragma unroll
    for (int off = 16; off; off >>= 1) {
        d1 += __shfl_xor_sync(0xffffffffu, d1, off);
        d2 += __shfl_xor_sync(0xffffffffu, d2, off);
    }
    if (lane == 0) { g_s1[row] = d1; g_s2[row] = d2; }
}

// ---------------------------------------------------------------------------
// Attention softmax row -> fp16 (normalized in fp32 before conversion).
// No max-shift; |e| small so exp is fp32-safe. One block per (b,i).
// ---------------------------------------------------------------------------
__global__ __launch_bounds__(256) void k_attn(const float* __restrict__ adj,
                                              __half* __restrict__ At) {
    const int i = blockIdx.x, b = blockIdx.y;
    __shared__ float sred[8];
    const float* ar  = adj + (size_t)i * Nn;
    const float* s2p = g_s2 + b * Nn;
    const float s1i = g_s1[b * Nn + i];
    const int j0 = threadIdx.x * 8;
    const int warp = threadIdx.x >> 5, lane = threadIdx.x & 31;

    float4 a0 = *(const float4*)(ar + j0),  a1 = *(const float4*)(ar + j0 + 4);
    float4 q0 = *(const float4*)(s2p + j0), q1 = *(const float4*)(s2p + j0 + 4);
    float av[8] = {a0.x, a0.y, a0.z, a0.w, a1.x, a1.y, a1.z, a1.w};
    float sv[8] = {q0.x, q0.y, q0.z, q0.w, q1.x, q1.y, q1.z, q1.w};

    float p[8], lsum = 0.f;
    #pragma unroll
    for (int k = 0; k < 8; k++) {
        float t = s1i + sv[k];
        t = (t >= 0.f) ? t : ALPHA * t;
        float v = (av[k] != 0.f) ? __expf(t) : 0.f;
        p[k] = v;
        lsum += v;
    }
    #pragma unroll
    for (int off = 16; off; off >>= 1) lsum += __shfl_xor_sync(0xffffffffu, lsum, off);
    if (lane == 0) sred[warp] = lsum;
    __syncthreads();
    if (warp == 0) {
        float v = (lane < 8) ? sred[lane] : 0.f;
        #pragma unroll
        for (int off = 4; off; off >>= 1) v += __shfl_xor_sync(0xffffffffu, v, off);
        if (lane == 0) sred[0] = v;
    }
    __syncthreads();
    const float inv = 1.f / sred[0];

    unsigned pk[4];
    #pragma unroll
    for (int k = 0; k < 4; k++)
        pk[k] = packh2(__float2half_rn(p[2 * k] * inv), __float2half_rn(p[2 * k + 1] * inv));
    *(uint4*)(At + ((size_t)b * Nn + i) * Nn + j0) = make_uint4(pk[0], pk[1], pk[2], pk[3]);
}

// ---------------------------------------------------------------------------
// Launch
// ---------------------------------------------------------------------------
extern "C" void kernel_launch(void* const* d_in, const int* in_sizes, int n_in,
                              void* d_out, int out_size) {
    const float* h   = (const float*)d_in[0];  // [8, 2048, 256]
    const float* adj = (const float*)d_in[1];  // [2048, 2048]
    const float* W   = (const float*)d_in[2];  // [256, 256]
    const float* a   = (const float*)d_in[3];  // [512, 1]
    float* out = (float*)d_out;                // [8, 2048, 256]

    __half *hf, *wt, *wht, *at;
    cudaGetSymbolAddress((void**)&hf,  g_hf);
    cudaGetSymbolAddress((void**)&wt,  g_wt);
    cudaGetSymbolAddress((void**)&wht, g_wht);
    cudaGetSymbolAddress((void**)&at,  g_at);

    cudaFuncSetAttribute(k_mma_gemm<0>, cudaFuncAttributeMaxDynamicSharedMemorySize, SMEM_G);
    cudaFuncSetAttribute(k_mma_gemm<1>, cudaFuncAttributeMaxDynamicSharedMemorySize, SMEM_G);

    k_prep_w<<<Ff, Ff>>>(W, a, wt);
    k_prep_h<<<(Bb * Nn) / 8, 256>>>(h, hf);

    // GEMM1 (fused transpose): WhT[b][o][n] = sum_f Wt[o,f] * h[b,n,f]
    //   A = Wt (M=256, K=256), B = h[b] (Ntot=2048, K=256)
    k_mma_gemm<1><<<dim3(Nn / 128, Ff / 128, Bb), 256, SMEM_G>>>(
        wt, hf, nullptr, wht, Nn, Ff, 0, (size_t)Nn * Ff, (size_t)Ff * Nn);

    // softmax rows -> attn fp16
    k_attn<<<dim3(Nn, Bb), 256>>>(adj, at);

    // GEMM2: out[b][i][o] = sum_k P[b][i][k] * WhT[b][o][k]
    //   A = P (M=2048, K=2048), B = WhT (Ntot=256, K=2048)
    k_mma_gemm<0><<<dim3(Ff / 128, Nn / 128, Bb), 256, SMEM_G>>>(
        at, wht, out, nullptr, Ff, Nn,
        (size_t)Nn * Nn, (size_t)Ff * Nn, (size_t)Nn * Ff);
}

// round 11
// speedup vs baseline: 1.4366x; 1.0021x over previous
#include <cuda_runtime.h>
#include <cuda_fp16.h>
#include <math.h>
#include <stdint.h>

#define ALPHA 0.2f

static constexpr int Bb = 8;     // batch
static constexpr int Nn = 2048;  // nodes
static constexpr int Ff = 256;   // features (Fin == Fout)

// ---------------------------------------------------------------------------
// Scratch (__device__ globals: allocation-free rule)
// ---------------------------------------------------------------------------
__device__ __align__(1024) __half g_hf[(size_t)Bb * Nn * Ff];     // h as fp16
__device__ __align__(1024) __half g_wt[Ff * Ff];                  // W^T fp16
__device__ __align__(1024) __half g_wht[(size_t)Bb * Ff * Nn];    // WhT fp16
__device__ __align__(1024) __half g_at[(size_t)Bb * Nn * Nn];     // attn fp16 (67 MB)
__device__ __align__(16)   float g_s1[Bb * Nn];
__device__ __align__(16)   float g_s2[Bb * Nn];
__device__ __align__(16)   float g_wa[2 * Ff];

// ---------------------------------------------------------------------------
// Helpers (baseline PTX only: mma.sync / ldmatrix / cp.async)
// ---------------------------------------------------------------------------
__device__ __forceinline__ uint32_t smem_u32(const void* p) {
    uint32_t a;
    asm("{ .reg .u64 t; cvta.to.shared.u64 t, %1; cvt.u32.u64 %0, t; }" : "=r"(a) : "l"(p));
    return a;
}
#define LDSM4(r0, r1, r2, r3, addr) \
    asm volatile("ldmatrix.sync.aligned.m8n8.x4.shared.b16 {%0,%1,%2,%3}, [%4];" \
                 : "=r"(r0), "=r"(r1), "=r"(r2), "=r"(r3) : "r"(addr))
#define MMA16816(d, a, b) \
    asm volatile("mma.sync.aligned.m16n8k16.row.col.f32.f16.f16.f32 " \
                 "{%0,%1,%2,%3},{%4,%5,%6,%7},{%8,%9},{%0,%1,%2,%3};" \
                 : "+f"((d)[0]), "+f"((d)[1]), "+f"((d)[2]), "+f"((d)[3]) \
                 : "r"((a)[0]), "r"((a)[1]), "r"((a)[2]), "r"((a)[3]), \
                   "r"((b)[0]), "r"((b)[1]))
#define CPA16(s, g) asm volatile("cp.async.cg.shared.global [%0], [%1], 16;" :: "r"(s), "l"(g))
#define CPCOMMIT()  asm volatile("cp.async.commit_group;" ::: "memory")
#define CPWAIT(n)   asm volatile("cp.async.wait_group %0;" :: "n"(n) : "memory")

__device__ __forceinline__ unsigned packh2(__half a, __half b) {
    __half2 t(a, b);
    return *reinterpret_cast<unsigned*>(&t);
}

// ---------------------------------------------------------------------------
// fp16 GEMM: C[M,Ntot] = A[M,K] @ B[Ntot,K]^T (both K-major)
// CTA 128x128, 8 warps (4m x 2n), warp tile 32x64, BK=64, 3-stage cp.async.
// 2 CTAs/SM (acc = 64 regs).  grid = (Ntot/128, M/128, batch)
// EPI=0: fp32 C.   EPI=1: fp16 Ch.
// ---------------------------------------------------------------------------
static constexpr int TSK    = 72;                 // padded row stride (fp16) for BK=64
static constexpr int TILE_K = 128 * TSK * 2;      // 18432 per 128-row tile
static constexpr int STAGE  = 2 * TILE_K;         // 36864 (A + B)
static constexpr int SMEM_G = 3 * STAGE;          // 110592

template<int EPI>
__global__ __launch_bounds__(256, 2) void k_mma_gemm(
    const __half* __restrict__ A0, const __half* __restrict__ B0,
    float* __restrict__ C, __half* __restrict__ Ch,
    int Ntot, int K, size_t sA, size_t sB, size_t sC)
{
    extern __shared__ __align__(128) char smem[];
    const int tid = threadIdx.x;
    const int wid = tid >> 5, lane = tid & 31;
    const int wm = (wid & 3) * 32;        // 4 m-warps
    const int wn = (wid >> 2) * 64;       // 2 n-warps
    const size_t bz = blockIdx.z;
    A0 += bz * sA;
    B0 += bz * sB;
    const int m0 = blockIdx.y * 128, n0 = blockIdx.x * 128;
    const uint32_t sb = smem_u32(smem);

    float acc[2][8][4];
    #pragma unroll
    for (int i = 0; i < 2; i++)
        #pragma unroll
        for (int j = 0; j < 8; j++)
            #pragma unroll
            for (int c = 0; c < 4; c++) acc[i][j][c] = 0.f;

    // loaders: each tile 128 rows x 8 chunks(16B) = 1024 chunks; 4/thread/tile
    auto issue = [&](int it, int buf) {
        const int k0 = it << 6;
        const uint32_t s = sb + buf * STAGE;
        #pragma unroll
        for (int r = 0; r < 4; r++) {
            int u = tid + r * 256;              // 0..1023
            int row = u >> 3, c = (u & 7) * 8;  // c in halves
            const uint32_t so = (uint32_t)(row * TSK + c) * 2;
            CPA16(s + so,          A0 + (size_t)(m0 + row) * K + k0 + c);
            CPA16(s + TILE_K + so, B0 + (size_t)(n0 + row) * K + k0 + c);
        }
    };

    const int l7 = lane & 7, lb3 = (lane >> 3) & 1, lb4 = lane >> 4;
    const int nch = K >> 6;

    issue(0, 0); CPCOMMIT();
    if (nch > 1) { issue(1, 1); CPCOMMIT(); }

    int buf = 0;
    for (int i = 0; i < nch; i++) {
        if (i + 2 < nch) { issue(i + 2, (buf + 2) % 3); CPCOMMIT(); CPWAIT(2); }
        else if (i + 1 < nch) { CPWAIT(1); }
        else { CPWAIT(0); }
        __syncthreads();

        const uint32_t s = sb + buf * STAGE;
        #pragma unroll
        for (int ks = 0; ks < 4; ks++) {
            const int ko = ks * 16;
            uint32_t af[2][4], bf[8][2];
            #pragma unroll
            for (int mf = 0; mf < 2; mf++) {
                int row = wm + mf * 16 + l7 + lb3 * 8;
                LDSM4(af[mf][0], af[mf][1], af[mf][2], af[mf][3],
                      s + (uint32_t)(row * TSK + ko + lb4 * 8) * 2);
            }
            #pragma unroll
            for (int nq = 0; nq < 4; nq++) {
                int nr = wn + nq * 16 + l7 + lb4 * 8;
                LDSM4(bf[nq * 2][0], bf[nq * 2][1], bf[nq * 2 + 1][0], bf[nq * 2 + 1][1],
                      s + TILE_K + (uint32_t)(nr * TSK + ko + lb3 * 8) * 2);
            }
            #pragma unroll
            for (int mf = 0; mf < 2; mf++)
                #pragma unroll
                for (int nf = 0; nf < 8; nf++) MMA16816(acc[mf][nf], af[mf], bf[nf]);
        }
        __syncthreads();
        buf = (buf + 1) % 3;
    }

    const int crow = m0 + wm + (lane >> 2);
    const int ccol = n0 + wn + (lane & 3) * 2;
    if (EPI == 0) {
        float* Cb = C + bz * sC;
        #pragma unroll
        for (int mf = 0; mf < 2; mf++)
            #pragma unroll
            for (int nf = 0; nf < 8; nf++) {
                float* p0 = Cb + (size_t)(crow + mf * 16)     * Ntot + ccol + nf * 8;
                float* p1 = Cb + (size_t)(crow + mf * 16 + 8) * Ntot + ccol + nf * 8;
                *(float2*)p0 = make_float2(acc[mf][nf][0], acc[mf][nf][1]);
                *(float2*)p1 = make_float2(acc[mf][nf][2], acc[mf][nf][3]);
            }
    } else {
        __half* Hb = Ch + bz * sC;
        #pragma unroll
        for (int mf = 0; mf < 2; mf++)
            #pragma unroll
            for (int nf = 0; nf < 8; nf++) {
                const size_t o0 = (size_t)(crow + mf * 16)     * Ntot + ccol + nf * 8;
                const size_t o1 = (size_t)(crow + mf * 16 + 8) * Ntot + ccol + nf * 8;
                *(unsigned*)(Hb + o0) = packh2(__float2half_rn(acc[mf][nf][0]),
                                               __float2half_rn(acc[mf][nf][1]));
                *(unsigned*)(Hb + o1) = packh2(__float2half_rn(acc[mf][nf][2]),
                                               __float2half_rn(acc[mf][nf][3]));
            }
    }
}

// ---------------------------------------------------------------------------
// Prep W: Wt fp16 (block o transposes col o); block 0 also computes wa1/wa2.
// ---------------------------------------------------------------------------
__global__ void k_prep_w(const float* __restrict__ W, const float* __restrict__ a,
                         __half* __restrict__ T) {
    const int o = blockIdx.x, f = threadIdx.x;
    T[(size_t)o * Ff + f] = __float2half_rn(W[(size_t)f * Ff + o]);
    if (o == 0) {
        float d1 = 0.f, d2 = 0.f;
        const float* wrow = W + (size_t)f * Ff;
        #pragma unroll 8
        for (int j = 0; j < Ff; j++) {
            float w = wrow[j];
            d1 += w * a[j];
            d2 += w * a[Ff + j];
        }
        g_wa[f] = d1;
        g_wa[Ff + f] = d2;
    }
}

// ---------------------------------------------------------------------------
// Prep h: fp16 conversion + s1/s2 dots (reads h exactly once). Warp per row.
// ---------------------------------------------------------------------------
__global__ __launch_bounds__(256) void k_prep_h(const float* __restrict__ h,
                                                __half* __restrict__ hf) {
    __shared__ float swa[2 * Ff];
    for (int i = threadIdx.x; i < 2 * Ff; i += 256) swa[i] = g_wa[i];
    __syncthreads();

    const int warp = threadIdx.x >> 5, lane = threadIdx.x & 31;
    const int row = blockIdx.x * 8 + warp;
    const float* hp = h + (size_t)row * Ff;
    const int j0 = lane * 8;

    float4 v0 = *(const float4*)(hp + j0), v1 = *(const float4*)(hp + j0 + 4);
    float v[8] = {v0.x, v0.y, v0.z, v0.w, v1.x, v1.y, v1.z, v1.w};

    unsigned pk[4];
    #pragma unroll
    for (int k = 0; k < 4; k++)
        pk[k] = packh2(__float2half_rn(v[2 * k]), __float2half_rn(v[2 * k + 1]));
    *(uint4*)(hf + (size_t)row * Ff + j0) = make_uint4(pk[0], pk[1], pk[2], pk[3]);

    float d1 = 0.f, d2 = 0.f;
    #pragma unroll
    for (int k = 0; k < 8; k++) {
        d1 += v[k] * swa[j0 + k];
        d2 += v[k] * swa[Ff + j0 + k];
    }
    #pragma unroll
    for (int off = 16; off; off >>= 1) {
        d1 += __shfl_xor_sync(0xffffffffu, d1, off);
        d2 += __shfl_xor_sync(0xffffffffu, d2, off);
    }
    if (lane == 0) { g_s1[row] = d1; g_s2[row] = d2; }
}

// ---------------------------------------------------------------------------
// Attention softmax: ONE block per node i, loop over all 8 batches.
// adj row loaded once (registers); all 8 rowsums reduced in one combined
// block reduction (2 syncs total). Writes normalized fp16 probs.
// ---------------------------------------------------------------------------
__global__ __launch_bounds__(256) void k_attn(const float* __restrict__ adj,
                                              __half* __restrict__ At) {
    const int i = blockIdx.x;
    const int tid = threadIdx.x;
    const int warp = tid >> 5, lane = tid & 31;
    const int j0 = tid * 8;
    __shared__ float sred[8 * Bb];   // [warp][b]
    __shared__ float sinv[Bb];

    const float* ar = adj + (size_t)i * Nn;
    float4 a0 = *(const float4*)(ar + j0), a1 = *(const float4*)(ar + j0 + 4);
    float av[8] = {a0.x, a0.y, a0.z, a0.w, a1.x, a1.y, a1.z, a1.w};

    float p[Bb][8];
    float lsum[Bb];
    #pragma unroll
    for (int b = 0; b < Bb; b++) {
        const float s1i = g_s1[b * Nn + i];
        const float* s2p = g_s2 + b * Nn + j0;
        float4 q0 = *(const float4*)(s2p), q1 = *(const float4*)(s2p + 4);
        float sv[8] = {q0.x, q0.y, q0.z, q0.w, q1.x, q1.y, q1.z, q1.w};
        float ls = 0.f;
        #pragma unroll
        for (int k = 0; k < 8; k++) {
            float t = s1i + sv[k];
            t = (t >= 0.f) ? t : ALPHA * t;
            float pv = (av[k] != 0.f) ? __expf(t) : 0.f;
            p[b][k] = pv;
            ls += pv;
        }
        lsum[b] = ls;
    }

    // combined block reduction for all 8 batch sums
    #pragma unroll
    for (int b = 0; b < Bb; b++) {
        #pragma unroll
        for (int off = 16; off; off >>= 1)
            lsum[b] += __shfl_xor_sync(0xffffffffu, lsum[b], off);
    }
    if (lane == 0) {
        #pragma unroll
        for (int b = 0; b < Bb; b++) sred[warp * Bb + b] = lsum[b];
    }
    __syncthreads();
    if (tid < Bb) {
        float s = 0.f;
        #pragma unroll
        for (int w = 0; w < 8; w++) s += sred[w * Bb + tid];
        sinv[tid] = 1.f / s;
    }
    __syncthreads();

    #pragma unroll
    for (int b = 0; b < Bb; b++) {
        const float inv = sinv[b];
        unsigned pk[4];
        #pragma unroll
        for (int k = 0; k < 4; k++)
            pk[k] = packh2(__float2half_rn(p[b][2 * k] * inv),
                           __float2half_rn(p[b][2 * k + 1] * inv));
        *(uint4*)(At + ((size_t)b * Nn + i) * Nn + j0) = make_uint4(pk[0], pk[1], pk[2], pk[3]);
    }
}

// ---------------------------------------------------------------------------
// Launch
// ---------------------------------------------------------------------------
extern "C" void kernel_launch(void* const* d_in, const int* in_sizes, int n_in,
                              void* d_out, int out_size) {
    const float* h   = (const float*)d_in[0];  // [8, 2048, 256]
    const float* adj = (const float*)d_in[1];  // [2048, 2048]
    const float* W   = (const float*)d_in[2];  // [256, 256]
    const float* a   = (const float*)d_in[3];  // [512, 1]
    float* out = (float*)d_out;                // [8, 2048, 256]

    __half *hf, *wt, *wht, *at;
    cudaGetSymbolAddress((void**)&hf,  g_hf);
    cudaGetSymbolAddress((void**)&wt,  g_wt);
    cudaGetSymbolAddress((void**)&wht, g_wht);
    cudaGetSymbolAddress((void**)&at,  g_at);

    cudaFuncSetAttribute(k_mma_gemm<0>, cudaFuncAttributeMaxDynamicSharedMemorySize, SMEM_G);
    cudaFuncSetAttribute(k_mma_gemm<1>, cudaFuncAttributeMaxDynamicSharedMemorySize, SMEM_G);

    k_prep_w<<<Ff, Ff>>>(W, a, wt);
    k_prep_h<<<(Bb * Nn) / 8, 256>>>(h, hf);

    // GEMM1 (fused transpose): WhT[b][o][n] = sum_f Wt[o,f] * h[b,n,f]
    //   A = Wt (M=256, K=256), B = h[b] (Ntot=2048, K=256)
    k_mma_gemm<1><<<dim3(Nn / 128, Ff / 128, Bb), 256, SMEM_G>>>(
        wt, hf, nullptr, wht, Nn, Ff, 0, (size_t)Nn * Ff, (size_t)Ff * Nn);

    // softmax rows -> attn fp16 (one block per node, all batches)
    k_attn<<<Nn, 256>>>(adj, at);

    // GEMM2: out[b][i][o] = sum_k P[b][i][k] * WhT[b][o][k]
    //   A = P (M=2048, K=2048), B = WhT (Ntot=256, K=2048)
    k_mma_gemm<0><<<dim3(Ff / 128, Nn / 128, Bb), 256, SMEM_G>>>(
        at, wht, out, nullptr, Ff, Nn,
        (size_t)Nn * Nn, (size_t)Ff * Nn, (size_t)Nn * Ff);
}

// round 12
// speedup vs baseline: 1.5603x; 1.0861x over previous
#include <cuda_runtime.h>
#include <cuda_fp16.h>
#include <math.h>
#include <stdint.h>

#define ALPHA 0.2f

static constexpr int Bb = 8;     // batch
static constexpr int Nn = 2048;  // nodes
static constexpr int Ff = 256;   // features (Fin == Fout)

// ---------------------------------------------------------------------------
// Scratch (__device__ globals: allocation-free rule)
// ---------------------------------------------------------------------------
__device__ __align__(1024) __half g_hf[(size_t)Bb * Nn * Ff];     // h as fp16
__device__ __align__(1024) __half g_wt[Ff * Ff];                  // W^T fp16
__device__ __align__(1024) __half g_wht[(size_t)Bb * Ff * Nn];    // WhT fp16
__device__ __align__(1024) __half g_at[(size_t)Bb * Nn * Nn];     // attn fp16 (67 MB)
__device__ __align__(16)   float g_s1[Bb * Nn];
__device__ __align__(16)   float g_s2[Bb * Nn];
__device__ __align__(16)   float g_wa[2 * Ff];

// ---------------------------------------------------------------------------
// Helpers (baseline PTX only: mma.sync / ldmatrix / cp.async)
// ---------------------------------------------------------------------------
__device__ __forceinline__ uint32_t smem_u32(const void* p) {
    uint32_t a;
    asm("{ .reg .u64 t; cvta.to.shared.u64 t, %1; cvt.u32.u64 %0, t; }" : "=r"(a) : "l"(p));
    return a;
}
#define LDSM4(r0, r1, r2, r3, addr) \
    asm volatile("ldmatrix.sync.aligned.m8n8.x4.shared.b16 {%0,%1,%2,%3}, [%4];" \
                 : "=r"(r0), "=r"(r1), "=r"(r2), "=r"(r3) : "r"(addr))
#define MMA16816(d, a, b) \
    asm volatile("mma.sync.aligned.m16n8k16.row.col.f32.f16.f16.f32 " \
                 "{%0,%1,%2,%3},{%4,%5,%6,%7},{%8,%9},{%0,%1,%2,%3};" \
                 : "+f"((d)[0]), "+f"((d)[1]), "+f"((d)[2]), "+f"((d)[3]) \
                 : "r"((a)[0]), "r"((a)[1]), "r"((a)[2]), "r"((a)[3]), \
                   "r"((b)[0]), "r"((b)[1]))
#define CPA16(s, g) asm volatile("cp.async.cg.shared.global [%0], [%1], 16;" :: "r"(s), "l"(g))
#define CPCOMMIT()  asm volatile("cp.async.commit_group;" ::: "memory")
#define CPWAIT(n)   asm volatile("cp.async.wait_group %0;" :: "n"(n) : "memory")

__device__ __forceinline__ unsigned packh2(__half a, __half b) {
    __half2 t(a, b);
    return *reinterpret_cast<unsigned*>(&t);
}

// ---------------------------------------------------------------------------
// fp16 GEMM: C[M,Ntot] = A[M,K] @ B[Ntot,K]^T (both K-major)
// CTA 128x128, 8 warps (4m x 2n), warp tile 32x64, BK=64, 3-stage cp.async.
// 2 CTAs/SM (acc = 64 regs).  grid = (Ntot/128, M/128, batch)
// EPI=0: fp32 C.   EPI=1: fp16 Ch.
// ---------------------------------------------------------------------------
static constexpr int TSK    = 72;                 // padded row stride (fp16) for BK=64
static constexpr int TILE_K = 128 * TSK * 2;      // 18432 per 128-row tile
static constexpr int STAGE  = 2 * TILE_K;         // 36864 (A + B)
static constexpr int SMEM_G = 3 * STAGE;          // 110592

template<int EPI>
__global__ __launch_bounds__(256, 2) void k_mma_gemm(
    const __half* __restrict__ A0, const __half* __restrict__ B0,
    float* __restrict__ C, __half* __restrict__ Ch,
    int Ntot, int K, size_t sA, size_t sB, size_t sC)
{
    extern __shared__ __align__(128) char smem[];
    const int tid = threadIdx.x;
    const int wid = tid >> 5, lane = tid & 31;
    const int wm = (wid & 3) * 32;        // 4 m-warps
    const int wn = (wid >> 2) * 64;       // 2 n-warps
    const size_t bz = blockIdx.z;
    A0 += bz * sA;
    B0 += bz * sB;
    const int m0 = blockIdx.y * 128, n0 = blockIdx.x * 128;
    const uint32_t sb = smem_u32(smem);

    float acc[2][8][4];
    #pragma unroll
    for (int i = 0; i < 2; i++)
        #pragma unroll
        for (int j = 0; j < 8; j++)
            #pragma unroll
            for (int c = 0; c < 4; c++) acc[i][j][c] = 0.f;

    // loaders: each tile 128 rows x 8 chunks(16B) = 1024 chunks; 4/thread/tile
    auto issue = [&](int it, int buf) {
        const int k0 = it << 6;
        const uint32_t s = sb + buf * STAGE;
        #pragma unroll
        for (int r = 0; r < 4; r++) {
            int u = tid + r * 256;              // 0..1023
            int row = u >> 3, c = (u & 7) * 8;  // c in halves
            const uint32_t so = (uint32_t)(row * TSK + c) * 2;
            CPA16(s + so,          A0 + (size_t)(m0 + row) * K + k0 + c);
            CPA16(s + TILE_K + so, B0 + (size_t)(n0 + row) * K + k0 + c);
        }
    };

    const int l7 = lane & 7, lb3 = (lane >> 3) & 1, lb4 = lane >> 4;
    const int nch = K >> 6;

    issue(0, 0); CPCOMMIT();
    if (nch > 1) { issue(1, 1); CPCOMMIT(); }

    int buf = 0;
    for (int i = 0; i < nch; i++) {
        if (i + 2 < nch) { issue(i + 2, (buf + 2) % 3); CPCOMMIT(); CPWAIT(2); }
        else if (i + 1 < nch) { CPWAIT(1); }
        else { CPWAIT(0); }
        __syncthreads();

        const uint32_t s = sb + buf * STAGE;
        #pragma unroll
        for (int ks = 0; ks < 4; ks++) {
            const int ko = ks * 16;
            uint32_t af[2][4], bf[8][2];
            #pragma unroll
            for (int mf = 0; mf < 2; mf++) {
                int row = wm + mf * 16 + l7 + lb3 * 8;
                LDSM4(af[mf][0], af[mf][1], af[mf][2], af[mf][3],
                      s + (uint32_t)(row * TSK + ko + lb4 * 8) * 2);
            }
            #pragma unroll
            for (int nq = 0; nq < 4; nq++) {
                int nr = wn + nq * 16 + l7 + lb4 * 8;
                LDSM4(bf[nq * 2][0], bf[nq * 2][1], bf[nq * 2 + 1][0], bf[nq * 2 + 1][1],
                      s + TILE_K + (uint32_t)(nr * TSK + ko + lb3 * 8) * 2);
            }
            #pragma unroll
            for (int mf = 0; mf < 2; mf++)
                #pragma unroll
                for (int nf = 0; nf < 8; nf++) MMA16816(acc[mf][nf], af[mf], bf[nf]);
        }
        __syncthreads();
        buf = (buf + 1) % 3;
    }

    const int crow = m0 + wm + (lane >> 2);
    const int ccol = n0 + wn + (lane & 3) * 2;
    if (EPI == 0) {
        float* Cb = C + bz * sC;
        #pragma unroll
        for (int mf = 0; mf < 2; mf++)
            #pragma unroll
            for (int nf = 0; nf < 8; nf++) {
                float* p0 = Cb + (size_t)(crow + mf * 16)     * Ntot + ccol + nf * 8;
                float* p1 = Cb + (size_t)(crow + mf * 16 + 8) * Ntot + ccol + nf * 8;
                *(float2*)p0 = make_float2(acc[mf][nf][0], acc[mf][nf][1]);
                *(float2*)p1 = make_float2(acc[mf][nf][2], acc[mf][nf][3]);
            }
    } else {
        __half* Hb = Ch + bz * sC;
        #pragma unroll
        for (int mf = 0; mf < 2; mf++)
            #pragma unroll
            for (int nf = 0; nf < 8; nf++) {
                const size_t o0 = (size_t)(crow + mf * 16)     * Ntot + ccol + nf * 8;
                const size_t o1 = (size_t)(crow + mf * 16 + 8) * Ntot + ccol + nf * 8;
                *(unsigned*)(Hb + o0) = packh2(__float2half_rn(acc[mf][nf][0]),
                                               __float2half_rn(acc[mf][nf][1]));
                *(unsigned*)(Hb + o1) = packh2(__float2half_rn(acc[mf][nf][2]),
                                               __float2half_rn(acc[mf][nf][3]));
            }
    }
}

// ---------------------------------------------------------------------------
// Prep W: Wt fp16 (block o transposes col o); block 0 also computes wa1/wa2.
// ---------------------------------------------------------------------------
__global__ void k_prep_w(const float* __restrict__ W, const float* __restrict__ a,
                         __half* __restrict__ T) {
    const int o = blockIdx.x, f = threadIdx.x;
    T[(size_t)o * Ff + f] = __float2half_rn(W[(size_t)f * Ff + o]);
    if (o == 0) {
        float d1 = 0.f, d2 = 0.f;
        const float* wrow = W + (size_t)f * Ff;
        #pragma unroll 8
        for (int j = 0; j < Ff; j++) {
            float w = wrow[j];
            d1 += w * a[j];
            d2 += w * a[Ff + j];
        }
        g_wa[f] = d1;
        g_wa[Ff + f] = d2;
    }
}

// ---------------------------------------------------------------------------
// Prep h: fp16 conversion + s1/s2 dots (reads h exactly once). Warp per row.
// ---------------------------------------------------------------------------
__global__ __launch_bounds__(256) void k_prep_h(const float* __restrict__ h,
                                                __half* __restrict__ hf) {
    __shared__ float swa[2 * Ff];
    for (int i = threadIdx.x; i < 2 * Ff; i += 256) swa[i] = g_wa[i];
    __syncthreads();

    const int warp = threadIdx.x >> 5, lane = threadIdx.x & 31;
    const int row = blockIdx.x * 8 + warp;
    const float* hp = h + (size_t)row * Ff;
    const int j0 = lane * 8;

    float4 v0 = *(const float4*)(hp + j0), v1 = *(const float4*)(hp + j0 + 4);
    float v[8] = {v0.x, v0.y, v0.z, v0.w, v1.x, v1.y, v1.z, v1.w};

    unsigned pk[4];
    #pragma unroll
    for (int k = 0; k < 4; k++)
        pk[k] = packh2(__float2half_rn(v[2 * k]), __float2half_rn(v[2 * k + 1]));
    *(uint4*)(hf + (size_t)row * Ff + j0) = make_uint4(pk[0], pk[1], pk[2], pk[3]);

    float d1 = 0.f, d2 = 0.f;
    #pragma unroll
    for (int k = 0; k < 8; k++) {
        d1 += v[k] * swa[j0 + k];
        d2 += v[k] * swa[Ff + j0 + k];
    }
    #pragma unroll
    for (int off = 16; off; off >>= 1) {
        d1 += __shfl_xor_sync(0xffffffffu, d1, off);
        d2 += __shfl_xor_sync(0xffffffffu, d2, off);
    }
    if (lane == 0) { g_s1[row] = d1; g_s2[row] = d2; }
}

// ---------------------------------------------------------------------------
// Attention softmax: one block per node i handles TWO batches (adj row loaded
// once, reused). Low register footprint -> high occupancy. grid (Nn, Bb/2).
// ---------------------------------------------------------------------------
__global__ __launch_bounds__(256) void k_attn(const float* __restrict__ adj,
                                              __half* __restrict__ At) {
    const int i = blockIdx.x;
    const int b0 = blockIdx.y * 2;
    const int tid = threadIdx.x;
    const int warp = tid >> 5, lane = tid & 31;
    const int j0 = tid * 8;
    __shared__ float sred[8 * 2];
    __shared__ float sinv[2];

    const float* ar = adj + (size_t)i * Nn;
    float4 a0 = *(const float4*)(ar + j0), a1 = *(const float4*)(ar + j0 + 4);
    float av[8] = {a0.x, a0.y, a0.z, a0.w, a1.x, a1.y, a1.z, a1.w};

    float p[2][8], lsum[2];
    #pragma unroll
    for (int q = 0; q < 2; q++) {
        const int b = b0 + q;
        const float s1i = g_s1[b * Nn + i];
        const float* s2p = g_s2 + b * Nn + j0;
        float4 q0 = *(const float4*)(s2p), q1 = *(const float4*)(s2p + 4);
        float sv[8] = {q0.x, q0.y, q0.z, q0.w, q1.x, q1.y, q1.z, q1.w};
        float ls = 0.f;
        #pragma unroll
        for (int k = 0; k < 8; k++) {
            float t = s1i + sv[k];
            t = (t >= 0.f) ? t : ALPHA * t;
            float pv = (av[k] != 0.f) ? __expf(t) : 0.f;
            p[q][k] = pv;
            ls += pv;
        }
        lsum[q] = ls;
    }

    #pragma unroll
    for (int q = 0; q < 2; q++) {
        #pragma unroll
        for (int off = 16; off; off >>= 1)
            lsum[q] += __shfl_xor_sync(0xffffffffu, lsum[q], off);
    }
    if (lane == 0) { sred[warp * 2] = lsum[0]; sred[warp * 2 + 1] = lsum[1]; }
    __syncthreads();
    if (tid < 2) {
        float s = 0.f;
        #pragma unroll
        for (int w = 0; w < 8; w++) s += sred[w * 2 + tid];
        sinv[tid] = 1.f / s;
    }
    __syncthreads();

    #pragma unroll
    for (int q = 0; q < 2; q++) {
        const float inv = sinv[q];
        unsigned pk[4];
        #pragma unroll
        for (int k = 0; k < 4; k++)
            pk[k] = packh2(__float2half_rn(p[q][2 * k] * inv),
                           __float2half_rn(p[q][2 * k + 1] * inv));
        *(uint4*)(At + ((size_t)(b0 + q) * Nn + i) * Nn + j0) =
            make_uint4(pk[0], pk[1], pk[2], pk[3]);
    }
}

// ---------------------------------------------------------------------------
// Launch
// ---------------------------------------------------------------------------
extern "C" void kernel_launch(void* const* d_in, const int* in_sizes, int n_in,
                              void* d_out, int out_size) {
    const float* h   = (const float*)d_in[0];  // [8, 2048, 256]
    const float* adj = (const float*)d_in[1];  // [2048, 2048]
    const float* W   = (const float*)d_in[2];  // [256, 256]
    const float* a   = (const float*)d_in[3];  // [512, 1]
    float* out = (float*)d_out;                // [8, 2048, 256]

    __half *hf, *wt, *wht, *at;
    cudaGetSymbolAddress((void**)&hf,  g_hf);
    cudaGetSymbolAddress((void**)&wt,  g_wt);
    cudaGetSymbolAddress((void**)&wht, g_wht);
    cudaGetSymbolAddress((void**)&at,  g_at);

    cudaFuncSetAttribute(k_mma_gemm<0>, cudaFuncAttributeMaxDynamicSharedMemorySize, SMEM_G);
    cudaFuncSetAttribute(k_mma_gemm<1>, cudaFuncAttributeMaxDynamicSharedMemorySize, SMEM_G);

    k_prep_w<<<Ff, Ff>>>(W, a, wt);
    k_prep_h<<<(Bb * Nn) / 8, 256>>>(h, hf);

    // GEMM1 (fused transpose): WhT[b][o][n] = sum_f Wt[o,f] * h[b,n,f]
    //   A = Wt (M=256, K=256), B = h[b] (Ntot=2048, K=256)
    k_mma_gemm<1><<<dim3(Nn / 128, Ff / 128, Bb), 256, SMEM_G>>>(
        wt, hf, nullptr, wht, Nn, Ff, 0, (size_t)Nn * Ff, (size_t)Ff * Nn);

    // softmax rows -> attn fp16 (one block per node, 2 batches each)
    k_attn<<<dim3(Nn, Bb / 2), 256>>>(adj, at);

    // GEMM2: out[b][i][o] = sum_k P[b][i][k] * WhT[b][o][k]
    //   A = P (M=2048, K=2048), B = WhT (Ntot=256, K=2048)
    k_mma_gemm<0><<<dim3(Ff / 128, Nn / 128, Bb), 256, SMEM_G>>>(
        at, wht, out, nullptr, Ff, Nn,
        (size_t)Nn * Nn, (size_t)Ff * Nn, (size_t)Nn * Ff);
}

// round 13
// speedup vs baseline: 1.6033x; 1.0276x over previous
#include <cuda_runtime.h>
#include <cuda_fp16.h>
#include <math.h>
#include <stdint.h>

#define ALPHA 0.2f

static constexpr int Bb = 8;     // batch
static constexpr int Nn = 2048;  // nodes
static constexpr int Ff = 256;   // features (Fin == Fout)

// ---------------------------------------------------------------------------
// Scratch (__device__ globals: allocation-free rule)
// ---------------------------------------------------------------------------
__device__ __align__(1024) __half g_hf[(size_t)Bb * Nn * Ff];     // h as fp16
__device__ __align__(1024) __half g_wt[Ff * Ff];                  // W^T fp16
__device__ __align__(1024) __half g_wht[(size_t)Bb * Ff * Nn];    // WhT fp16
__device__ __align__(1024) __half g_at[(size_t)Bb * Nn * Nn];     // attn fp16 (67 MB)
__device__ __align__(16)   float g_s1[Bb * Nn];
__device__ __align__(16)   float g_s2[Bb * Nn];
__device__ __align__(16)   float g_wa[2 * Ff];

// ---------------------------------------------------------------------------
// Helpers (baseline PTX only: mma.sync / ldmatrix / cp.async)
// ---------------------------------------------------------------------------
__device__ __forceinline__ uint32_t smem_u32(const void* p) {
    uint32_t a;
    asm("{ .reg .u64 t; cvta.to.shared.u64 t, %1; cvt.u32.u64 %0, t; }" : "=r"(a) : "l"(p));
    return a;
}
#define LDSM4(r0, r1, r2, r3, addr) \
    asm volatile("ldmatrix.sync.aligned.m8n8.x4.shared.b16 {%0,%1,%2,%3}, [%4];" \
                 : "=r"(r0), "=r"(r1), "=r"(r2), "=r"(r3) : "r"(addr))
#define MMA16816(d, a, b) \
    asm volatile("mma.sync.aligned.m16n8k16.row.col.f32.f16.f16.f32 " \
                 "{%0,%1,%2,%3},{%4,%5,%6,%7},{%8,%9},{%0,%1,%2,%3};" \
                 : "+f"((d)[0]), "+f"((d)[1]), "+f"((d)[2]), "+f"((d)[3]) \
                 : "r"((a)[0]), "r"((a)[1]), "r"((a)[2]), "r"((a)[3]), \
                   "r"((b)[0]), "r"((b)[1]))
#define CPA16(s, g) asm volatile("cp.async.cg.shared.global [%0], [%1], 16;" :: "r"(s), "l"(g))
#define CPCOMMIT()  asm volatile("cp.async.commit_group;" ::: "memory")
#define CPWAIT(n)   asm volatile("cp.async.wait_group %0;" :: "n"(n) : "memory")

__device__ __forceinline__ unsigned packh2(__half a, __half b) {
    __half2 t(a, b);
    return *reinterpret_cast<unsigned*>(&t);
}

// ---------------------------------------------------------------------------
// fp16 GEMM: C[M,Ntot] = A[M,K] @ B[Ntot,K]^T (both K-major)
// CTA 128x128, 8 warps (4m x 2n), warp tile 32x64, BK=64, 3-stage cp.async,
// ONE __syncthreads per K-iteration (issue into (i+2)%3 after the sync is
// safe: that buffer was last read in iteration i-1, which the sync fences).
// 2 CTAs/SM.  grid = (Ntot/128, M/128, batch).  EPI=0: fp32 C. EPI=1: fp16 Ch.
// ---------------------------------------------------------------------------
static constexpr int TSK    = 72;                 // padded row stride (fp16) for BK=64
static constexpr int TILE_K = 128 * TSK * 2;      // 18432 per 128-row tile
static constexpr int STAGE  = 2 * TILE_K;         // 36864 (A + B)
static constexpr int SMEM_G = 3 * STAGE;          // 110592

template<int EPI>
__global__ __launch_bounds__(256, 2) void k_mma_gemm(
    const __half* __restrict__ A0, const __half* __restrict__ B0,
    float* __restrict__ C, __half* __restrict__ Ch,
    int Ntot, int K, size_t sA, size_t sB, size_t sC)
{
    extern __shared__ __align__(128) char smem[];
    const int tid = threadIdx.x;
    const int wid = tid >> 5, lane = tid & 31;
    const int wm = (wid & 3) * 32;        // 4 m-warps
    const int wn = (wid >> 2) * 64;       // 2 n-warps
    const size_t bz = blockIdx.z;
    A0 += bz * sA;
    B0 += bz * sB;
    const int m0 = blockIdx.y * 128, n0 = blockIdx.x * 128;
    const uint32_t sb = smem_u32(smem);

    float acc[2][8][4];
    #pragma unroll
    for (int i = 0; i < 2; i++)
        #pragma unroll
        for (int j = 0; j < 8; j++)
            #pragma unroll
            for (int c = 0; c < 4; c++) acc[i][j][c] = 0.f;

    // loaders: each tile 128 rows x 8 chunks(16B) = 1024 chunks; 4/thread/tile
    auto issue = [&](int it, int buf) {
        const int k0 = it << 6;
        const uint32_t s = sb + buf * STAGE;
        #pragma unroll
        for (int r = 0; r < 4; r++) {
            int u = tid + r * 256;              // 0..1023
            int row = u >> 3, c = (u & 7) * 8;  // c in halves
            const uint32_t so = (uint32_t)(row * TSK + c) * 2;
            CPA16(s + so,          A0 + (size_t)(m0 + row) * K + k0 + c);
            CPA16(s + TILE_K + so, B0 + (size_t)(n0 + row) * K + k0 + c);
        }
    };

    const int l7 = lane & 7, lb3 = (lane >> 3) & 1, lb4 = lane >> 4;
    const int nch = K >> 6;

    issue(0, 0); CPCOMMIT();
    if (nch > 1) { issue(1, 1); CPCOMMIT(); }

    for (int i = 0; i < nch; i++) {
        if (i + 1 < nch) { CPWAIT(1); }   // stage i landed (only i+1 may be pending)
        else             { CPWAIT(0); }
        __syncthreads();                  // all warps done with MMA of i-1
        if (i + 2 < nch) { issue(i + 2, (i + 2) % 3); CPCOMMIT(); }

        const uint32_t s = sb + (i % 3) * STAGE;
        #pragma unroll
        for (int ks = 0; ks < 4; ks++) {
            const int ko = ks * 16;
            uint32_t af[2][4], bf[8][2];
            #pragma unroll
            for (int mf = 0; mf < 2; mf++) {
                int row = wm + mf * 16 + l7 + lb3 * 8;
                LDSM4(af[mf][0], af[mf][1], af[mf][2], af[mf][3],
                      s + (uint32_t)(row * TSK + ko + lb4 * 8) * 2);
            }
            #pragma unroll
            for (int nq = 0; nq < 4; nq++) {
                int nr = wn + nq * 16 + l7 + lb4 * 8;
                LDSM4(bf[nq * 2][0], bf[nq * 2][1], bf[nq * 2 + 1][0], bf[nq * 2 + 1][1],
                      s + TILE_K + (uint32_t)(nr * TSK + ko + lb3 * 8) * 2);
            }
            #pragma unroll
            for (int mf = 0; mf < 2; mf++)
                #pragma unroll
                for (int nf = 0; nf < 8; nf++) MMA16816(acc[mf][nf], af[mf], bf[nf]);
        }
    }

    const int crow = m0 + wm + (lane >> 2);
    const int ccol = n0 + wn + (lane & 3) * 2;
    if (EPI == 0) {
        float* Cb = C + bz * sC;
        #pragma unroll
        for (int mf = 0; mf < 2; mf++)
            #pragma unroll
            for (int nf = 0; nf < 8; nf++) {
                float* p0 = Cb + (size_t)(crow + mf * 16)     * Ntot + ccol + nf * 8;
                float* p1 = Cb + (size_t)(crow + mf * 16 + 8) * Ntot + ccol + nf * 8;
                *(float2*)p0 = make_float2(acc[mf][nf][0], acc[mf][nf][1]);
                *(float2*)p1 = make_float2(acc[mf][nf][2], acc[mf][nf][3]);
            }
    } else {
        __half* Hb = Ch + bz * sC;
        #pragma unroll
        for (int mf = 0; mf < 2; mf++)
            #pragma unroll
            for (int nf = 0; nf < 8; nf++) {
                const size_t o0 = (size_t)(crow + mf * 16)     * Ntot + ccol + nf * 8;
                const size_t o1 = (size_t)(crow + mf * 16 + 8) * Ntot + ccol + nf * 8;
                *(unsigned*)(Hb + o0) = packh2(__float2half_rn(acc[mf][nf][0]),
                                               __float2half_rn(acc[mf][nf][1]));
                *(unsigned*)(Hb + o1) = packh2(__float2half_rn(acc[mf][nf][2]),
                                               __float2half_rn(acc[mf][nf][3]));
            }
    }
}

// ---------------------------------------------------------------------------
// Prep W: Wt fp16 (block o transposes col o); block 0 also computes wa1/wa2.
// ---------------------------------------------------------------------------
__global__ void k_prep_w(const float* __restrict__ W, const float* __restrict__ a,
                         __half* __restrict__ T) {
    const int o = blockIdx.x, f = threadIdx.x;
    T[(size_t)o * Ff + f] = __float2half_rn(W[(size_t)f * Ff + o]);
    if (o == 0) {
        float d1 = 0.f, d2 = 0.f;
        const float* wrow = W + (size_t)f * Ff;
        #pragma unroll 8
        for (int j = 0; j < Ff; j++) {
            float w = wrow[j];
            d1 += w * a[j];
            d2 += w * a[Ff + j];
        }
        g_wa[f] = d1;
        g_wa[Ff + f] = d2;
    }
}

// ---------------------------------------------------------------------------
// Prep h: fp16 conversion + s1/s2 dots (reads h exactly once). Warp per row.
// ---------------------------------------------------------------------------
__global__ __launch_bounds__(256) void k_prep_h(const float* __restrict__ h,
                                                __half* __restrict__ hf) {
    __shared__ float swa[2 * Ff];
    for (int i = threadIdx.x; i < 2 * Ff; i += 256) swa[i] = g_wa[i];
    __syncthreads();

    const int warp = threadIdx.x >> 5, lane = threadIdx.x & 31;
    const int row = blockIdx.x * 8 + warp;
    const float* hp = h + (size_t)row * Ff;
    const int j0 = lane * 8;

    float4 v0 = *(const float4*)(hp + j0), v1 = *(const float4*)(hp + j0 + 4);
    float v[8] = {v0.x, v0.y, v0.z, v0.w, v1.x, v1.y, v1.z, v1.w};

    unsigned pk[4];
    #pragma unroll
    for (int k = 0; k < 4; k++)
        pk[k] = packh2(__float2half_rn(v[2 * k]), __float2half_rn(v[2 * k + 1]));
    *(uint4*)(hf + (size_t)row * Ff + j0) = make_uint4(pk[0], pk[1], pk[2], pk[3]);

    float d1 = 0.f, d2 = 0.f;
    #pragma unroll
    for (int k = 0; k < 8; k++) {
        d1 += v[k] * swa[j0 + k];
        d2 += v[k] * swa[Ff + j0 + k];
    }
    #pragma unroll
    for (int off = 16; off; off >>= 1) {
        d1 += __shfl_xor_sync(0xffffffffu, d1, off);
        d2 += __shfl_xor_sync(0xffffffffu, d2, off);
    }
    if (lane == 0) { g_s1[row] = d1; g_s2[row] = d2; }
}

// ---------------------------------------------------------------------------
// Attention softmax: one block per node i handles TWO batches (adj row loaded
// once, reused). adj is exactly {0,1}, so mask = multiply (no select).
// ---------------------------------------------------------------------------
__global__ __launch_bounds__(256) void k_attn(const float* __restrict__ adj,
                                              __half* __restrict__ At) {
    const int i = blockIdx.x;
    const int b0 = blockIdx.y * 2;
    const int tid = threadIdx.x;
    const int warp = tid >> 5, lane = tid & 31;
    const int j0 = tid * 8;
    __shared__ float sred[8 * 2];
    __shared__ float sinv[2];

    const float* ar = adj + (size_t)i * Nn;
    float4 a0 = *(const float4*)(ar + j0), a1 = *(const float4*)(ar + j0 + 4);
    float av[8] = {a0.x, a0.y, a0.z, a0.w, a1.x, a1.y, a1.z, a1.w};

    float p[2][8], lsum[2];
    #pragma unroll
    for (int q = 0; q < 2; q++) {
        const int b = b0 + q;
        const float s1i = g_s1[b * Nn + i];
        const float* s2p = g_s2 + b * Nn + j0;
        float4 q0 = *(const float4*)(s2p), q1 = *(const float4*)(s2p + 4);
        float sv[8] = {q0.x, q0.y, q0.z, q0.w, q1.x, q1.y, q1.z, q1.w};
        float ls = 0.f;
        #pragma unroll
        for (int k = 0; k < 8; k++) {
            float t = s1i + sv[k];
            t = (t >= 0.f) ? t : ALPHA * t;
            float pv = av[k] * __expf(t);   // adj in {0,1}: multiply == mask
            p[q][k] = pv;
            ls += pv;
        }
        lsum[q] = ls;
    }

    #pragma unroll
    for (int q = 0; q < 2; q++) {
        #pragma unroll
        for (int off = 16; off; off >>= 1)
            lsum[q] += __shfl_xor_sync(0xffffffffu, lsum[q], off);
    }
    if (lane == 0) { sred[warp * 2] = lsum[0]; sred[warp * 2 + 1] = lsum[1]; }
    __syncthreads();
    if (tid < 2) {
        float s = 0.f;
        #pragma unroll
        for (int w = 0; w < 8; w++) s += sred[w * 2 + tid];
        sinv[tid] = 1.f / s;
    }
    __syncthreads();

    #pragma unroll
    for (int q = 0; q < 2; q++) {
        const float inv = sinv[q];
        unsigned pk[4];
        #pragma unroll
        for (int k = 0; k < 4; k++)
            pk[k] = packh2(__float2half_rn(p[q][2 * k] * inv),
                           __float2half_rn(p[q][2 * k + 1] * inv));
        *(uint4*)(At + ((size_t)(b0 + q) * Nn + i) * Nn + j0) =
            make_uint4(pk[0], pk[1], pk[2], pk[3]);
    }
}

// ---------------------------------------------------------------------------
// Launch
// ---------------------------------------------------------------------------
extern "C" void kernel_launch(void* const* d_in, const int* in_sizes, int n_in,
                              void* d_out, int out_size) {
    const float* h   = (const float*)d_in[0];  // [8, 2048, 256]
    const float* adj = (const float*)d_in[1];  // [2048, 2048]
    const float* W   = (const float*)d_in[2];  // [256, 256]
    const float* a   = (const float*)d_in[3];  // [512, 1]
    float* out = (float*)d_out;                // [8, 2048, 256]

    __half *hf, *wt, *wht, *at;
    cudaGetSymbolAddress((void**)&hf,  g_hf);
    cudaGetSymbolAddress((void**)&wt,  g_wt);
    cudaGetSymbolAddress((void**)&wht, g_wht);
    cudaGetSymbolAddress((void**)&at,  g_at);

    cudaFuncSetAttribute(k_mma_gemm<0>, cudaFuncAttributeMaxDynamicSharedMemorySize, SMEM_G);
    cudaFuncSetAttribute(k_mma_gemm<1>, cudaFuncAttributeMaxDynamicSharedMemorySize, SMEM_G);

    k_prep_w<<<Ff, Ff>>>(W, a, wt);
    k_prep_h<<<(Bb * Nn) / 8, 256>>>(h, hf);

    // GEMM1 (fused transpose): WhT[b][o][n] = sum_f Wt[o,f] * h[b,n,f]
    //   A = Wt (M=256, K=256), B = h[b] (Ntot=2048, K=256)
    k_mma_gemm<1><<<dim3(Nn / 128, Ff / 128, Bb), 256, SMEM_G>>>(
        wt, hf, nullptr, wht, Nn, Ff, 0, (size_t)Nn * Ff, (size_t)Ff * Nn);

    // softmax rows -> attn fp16 (one block per node, 2 batches each)
    k_attn<<<dim3(Nn, Bb / 2), 256>>>(adj, at);

    // GEMM2: out[b][i][o] = sum_k P[b][i][k] * WhT[b][o][k]
    //   A = P (M=2048, K=2048), B = WhT (Ntot=256, K=2048)
    k_mma_gemm<0><<<dim3(Ff / 128, Nn / 128, Bb), 256, SMEM_G>>>(
        at, wht, out, nullptr, Ff, Nn,
        (size_t)Nn * Nn, (size_t)Ff * Nn, (size_t)Nn * Ff);
}